// round 10
// baseline (speedup 1.0000x reference)
#include <cuda_runtime.h>
#include <cuda_fp16.h>
#include <mma.h>
#include <cstdint>

using namespace nvcuda;

#define NN 100000
#define NE_CAP 1600000
#define NF 128
#define FO3 40
#define FO3P 48
#define NWARP_CAP ((NE_CAP + 31) / 32 + 1)

typedef unsigned long long u64;

// ---------------- device scratch ----------------
__device__ float  g_deg[NN];
__device__ __half g_hh[(size_t)NN * NF];    // fp16 h (gather payload, layers 1,2)
__device__ float  g_h32[(size_t)NN * NF];   // fp32 h layer 3 (stride 48)
__device__ float  g_y32[(size_t)NN * NF];   // fp32 y (agg outputs, layers 1,2)
__device__ __half g_w2h[NF * NF];
__device__ __half g_w3h[NF * FO3P];
__device__ int2   g_sd[NE_CAP];
__device__ int2   g_epack[NE_CAP];          // {src, f32-bits norm}
__device__ int    g_rowptr[NN + 1];
__device__ int    g_wstart[NWARP_CAP];      // owning node of each 32-edge chunk
__device__ int    g_cur[NN];
__device__ int    g_cnt[NN];
__device__ int    g_bsum[128];
__device__ int    g_is32;

// ---------------- f32x2 helpers (layer-1 FFMA2 GEMM) ----------------
__device__ __forceinline__ void ffma2(u64& d, u64 a, u64 b) {
    asm("fma.rn.f32x2 %0, %1, %2, %0;" : "+l"(d) : "l"(a), "l"(b));
}
__device__ __forceinline__ u64 dup2(float x) {
    u64 r; asm("mov.b64 %0, {%1, %1};" : "=l"(r) : "f"(x)); return r;
}
__device__ __forceinline__ float2 upk2(u64 v) {
    float2 r; asm("mov.b64 {%0, %1}, %2;" : "=f"(r.x), "=f"(r.y) : "l"(v)); return r;
}
__device__ __forceinline__ void red4(float* p, float4 v) {
    asm volatile("red.global.add.v4.f32 [%0], {%1, %2, %3, %4};"
                 :: "l"(p), "f"(v.x), "f"(v.y), "f"(v.z), "f"(v.w) : "memory");
}

// ---------------- setup: zero + detect + W convert ----------------
__global__ void k_init(const long long* __restrict__ raw, int nE,
                       const float* __restrict__ W2, const float* __restrict__ W3,
                       __half* __restrict__ W2h, __half* __restrict__ W3h,
                       float* deg, int* cnt, int n) {
    int tid = threadIdx.x;
    int gid = blockIdx.x * blockDim.x + tid;
    int gsz = gridDim.x * blockDim.x;

    if (blockIdx.x == 0) {
        __shared__ int sflag;
        if (tid == 0) sflag = 0;
        __syncthreads();
        int lim = nE < 4096 ? nE : 4096;
        int bad = 0;
        for (int i = tid; i < lim; i += blockDim.x) {
            long long v = raw[i];
            if (v < 0 || v >= (1LL << 30)) bad = 1;
        }
        if (bad) atomicOr(&sflag, 1);
        __syncthreads();
        if (tid == 0) g_is32 = sflag;
    }
    for (int i = gid; i < n; i += gsz) { deg[i] = 0.f; cnt[i] = 0; }
    for (int i = gid; i < NF * NF; i += gsz) W2h[i] = __float2half(W2[i]);
    for (int i = gid; i < NF * FO3P; i += gsz) {
        int r = i / FO3P, c = i - r * FO3P;
        W3h[i] = (c < FO3) ? __float2half(W3[r * FO3 + c]) : __half(0);
    }
}

__global__ void k_prep(const void* __restrict__ raw, const float* __restrict__ ew,
                       float* deg, int* cnt, int nE) {
    int e = blockIdx.x * blockDim.x + threadIdx.x;
    if (e >= nE) return;
    int s, d;
    if (g_is32) {
        const int* p = (const int*)raw;
        s = p[e]; d = p[(size_t)nE + e];
    } else {
        const long long* p = (const long long*)raw;
        s = (int)p[e]; d = (int)p[(size_t)nE + e];
    }
    g_sd[e] = make_int2(s, d);
    atomicAdd(&deg[d], ew[e]);
    atomicAdd(&cnt[d], 1);
}

__global__ void k_scanA(const int* __restrict__ cnt, int* rowptr, int* bsum, int n) {
    __shared__ int s[1024];
    int t = threadIdx.x, i = blockIdx.x * 1024 + t;
    int v = (i < n) ? cnt[i] : 0;
    s[t] = v;
    __syncthreads();
#pragma unroll
    for (int off = 1; off < 1024; off <<= 1) {
        int x = (t >= off) ? s[t - off] : 0;
        __syncthreads();
        s[t] += x;
        __syncthreads();
    }
    if (i < n) rowptr[i] = s[t] - v;
    if (t == 1023) bsum[blockIdx.x] = s[1023];
}

__global__ void k_scanCB(int* rowptr, const int* __restrict__ bsum, int* cur,
                         float* deg, int n, int nE, int nb) {
    __shared__ int sb[128];
    int t = threadIdx.x;
    if (t < 128) sb[t] = (t < nb) ? bsum[t] : 0;
    __syncthreads();
#pragma unroll
    for (int off = 1; off < 128; off <<= 1) {
        int x = 0;
        if (t < 128 && t >= off) x = sb[t - off];
        __syncthreads();
        if (t < 128) sb[t] += x;
        __syncthreads();
    }
    int i = blockIdx.x * blockDim.x + t;
    if (i < n) {
        int j = i >> 10;
        int off = (j == 0) ? 0 : sb[j - 1];
        int v = rowptr[i] + off;
        rowptr[i] = v;
        cur[i] = v;
        deg[i] = rsqrtf(deg[i] + 1.0f);
    }
    if (i == 0) rowptr[n] = nE;
}

__global__ void k_place(const float* __restrict__ ew, const float* __restrict__ dinv,
                        int nE) {
    int e = blockIdx.x * blockDim.x + threadIdx.x;
    if (e >= nE) return;
    int2 sd = g_sd[e];
    int p = atomicAdd(&g_cur[sd.y], 1);
    float norm = ew[e] * dinv[sd.x] * dinv[sd.y];
    g_epack[p] = make_int2(sd.x, __float_as_int(norm));
}

// owning node of edge chunk w (largest node with rowptr[node] <= w*32)
__global__ void k_wstart(const int* __restrict__ rowptr, int* __restrict__ wstart,
                         int nwarp, int n) {
    int w = blockIdx.x * blockDim.x + threadIdx.x;
    if (w >= nwarp) return;
    int target = w * 32;
    int lo = 0, hi = n - 1;
    while (lo < hi) {
        int mid = (lo + hi + 1) >> 1;
        if (rowptr[mid] <= target) lo = mid; else hi = mid - 1;
    }
    wstart[w] = lo;
}

// ---------------- layer-1 GEMM (fp32, FFMA2) -> fp16 hh ----------------
__global__ void __launch_bounds__(256, 2)
k_gemm128_f32(const float* __restrict__ X, const float* __restrict__ W,
              __half* __restrict__ Hh, int n) {
    extern __shared__ float sm[];
    float* Ws = sm;
    float* Xs = sm + NF * NF;
    int tid = threadIdx.x, warp = tid >> 5, lane = tid & 31;

    for (int i = tid; i < NF * NF / 4; i += 256)
        ((float4*)Ws)[i] = ((const float4*)W)[i];

    int row0 = blockIdx.x * 64 + warp * 8;
    float* xs = Xs + warp * (8 * NF);
#pragma unroll
    for (int r = 0; r < 8; r++) {
        int row = row0 + r;
        float4 v = make_float4(0.f, 0.f, 0.f, 0.f);
        if (row < n) v = ((const float4*)(X + (size_t)row * NF))[lane];
        ((float4*)(xs + r * NF))[lane] = v;
    }
    __syncthreads();

    u64 acc[8][2];
#pragma unroll
    for (int r = 0; r < 8; r++) { acc[r][0] = 0ull; acc[r][1] = 0ull; }

    const float* wl = Ws + 4 * lane;
    for (int k4 = 0; k4 < NF; k4 += 4) {
        float4 xv[8];
#pragma unroll
        for (int r = 0; r < 8; r++)
            xv[r] = *(const float4*)(xs + r * NF + k4);
#pragma unroll
        for (int kk = 0; kk < 4; kk++) {
            const float* wp = wl + (k4 + kk) * NF;
            u64 w01 = *(const u64*)(wp);
            u64 w23 = *(const u64*)(wp + 2);
#pragma unroll
            for (int r = 0; r < 8; r++) {
                float xk = kk == 0 ? xv[r].x : kk == 1 ? xv[r].y
                         : kk == 2 ? xv[r].z : xv[r].w;
                u64 xk2 = dup2(xk);
                ffma2(acc[r][0], xk2, w01);
                ffma2(acc[r][1], xk2, w23);
            }
        }
    }
#pragma unroll
    for (int r = 0; r < 8; r++) {
        int row = row0 + r;
        if (row < n) {
            float2 a = upk2(acc[r][0]), b = upk2(acc[r][1]);
            __half2 h01 = __floats2half2_rn(a.x, a.y);
            __half2 h23 = __floats2half2_rn(b.x, b.y);
            ((uint2*)(Hh + (size_t)row * NF))[lane] =
                make_uint2(*(unsigned*)&h01, *(unsigned*)&h23);
        }
    }
}

// ---------------- layer-1 y init: y = b1 + dinv^2 * h1 ----------------
__global__ void k_init1(const __half* __restrict__ h, const float* __restrict__ bias,
                        const float* __restrict__ dinv, float* __restrict__ out,
                        long long tot) {
    long long i = (long long)blockIdx.x * blockDim.x + threadIdx.x;
    if (i >= tot) return;
    int node = (int)(i >> 5), g = (int)(i & 31);
    float dv = dinv[node];
    float s = dv * dv;
    uint2 hp = ((const uint2*)h)[i];
    float2 u = __half22float2(*(const __half2*)&hp.x);
    float2 v = __half22float2(*(const __half2*)&hp.y);
    float4 bv = ((const float4*)bias)[g];
    ((float4*)out)[i] = make_float4(fmaf(u.x, s, bv.x), fmaf(u.y, s, bv.y),
                                    fmaf(v.x, s, bv.z), fmaf(v.y, s, bv.w));
}

// ---------------- tc GEMM fout=128: fp32 X in, writes hh fp16 + Yinit fp32 ----------
__global__ void __launch_bounds__(256, 2)
k_gemm128_tc(const float* __restrict__ X, const __half* __restrict__ W,
             __half* __restrict__ Hh, const float* __restrict__ bias,
             const float* __restrict__ dinv, float* __restrict__ Yinit, int n) {
    extern __shared__ char smc[];
    __half* Ws = (__half*)smc;               // 32KB
    __half* Xs = (__half*)(smc + 32 * 1024); // 16KB
    int tid = threadIdx.x, wid = tid >> 5;
    int warp_m = wid >> 1, warp_n = wid & 1;
    int row0 = blockIdx.x * 64;

    for (int i = tid; i < 2048; i += 256)
        ((uint4*)Ws)[i] = ((const uint4*)W)[i];
    for (int i = tid; i < 1024; i += 256) {     // 64 rows x 16 uint4 (8 halves)
        int row = i >> 4, c = i & 15;
        uint4 v = make_uint4(0, 0, 0, 0);
        if (row0 + row < n) {
            const float4* xr = (const float4*)(X + (size_t)(row0 + row) * NF);
            float4 f0 = xr[c * 2], f1 = xr[c * 2 + 1];
            f0.x = fmaxf(f0.x, 0.f); f0.y = fmaxf(f0.y, 0.f);
            f0.z = fmaxf(f0.z, 0.f); f0.w = fmaxf(f0.w, 0.f);
            f1.x = fmaxf(f1.x, 0.f); f1.y = fmaxf(f1.y, 0.f);
            f1.z = fmaxf(f1.z, 0.f); f1.w = fmaxf(f1.w, 0.f);
            __half2 p0 = __floats2half2_rn(f0.x, f0.y);
            __half2 p1 = __floats2half2_rn(f0.z, f0.w);
            __half2 p2 = __floats2half2_rn(f1.x, f1.y);
            __half2 p3 = __floats2half2_rn(f1.z, f1.w);
            v = make_uint4(*(unsigned*)&p0, *(unsigned*)&p1,
                           *(unsigned*)&p2, *(unsigned*)&p3);
        }
        ((uint4*)Xs)[i] = v;
    }
    __syncthreads();

    wmma::fragment<wmma::accumulator, 16, 16, 16, float> c[4];
#pragma unroll
    for (int j = 0; j < 4; j++) wmma::fill_fragment(c[j], 0.f);

#pragma unroll
    for (int k0 = 0; k0 < NF; k0 += 16) {
        wmma::fragment<wmma::matrix_a, 16, 16, 16, __half, wmma::row_major> a;
        wmma::load_matrix_sync(a, Xs + warp_m * 16 * NF + k0, NF);
#pragma unroll
        for (int j = 0; j < 4; j++) {
            wmma::fragment<wmma::matrix_b, 16, 16, 16, __half, wmma::row_major> b;
            wmma::load_matrix_sync(b, Ws + k0 * NF + warp_n * 64 + j * 16, NF);
            wmma::mma_sync(c[j], a, b, c[j]);
        }
    }
    __syncthreads();
    float* Cs = (float*)smc;
#pragma unroll
    for (int j = 0; j < 4; j++)
        wmma::store_matrix_sync(Cs + warp_m * 16 * NF + warp_n * 64 + j * 16,
                                c[j], NF, wmma::mem_row_major);
    __syncthreads();

    for (int i = tid; i < 64 * 32; i += 256) {
        int row = i >> 5, g = i & 31;
        int grow = row0 + row;
        if (grow < n) {
            float4 v = ((const float4*)Cs)[i];
            __half2 h01 = __floats2half2_rn(v.x, v.y);
            __half2 h23 = __floats2half2_rn(v.z, v.w);
            ((uint2*)(Hh + (size_t)grow * NF))[g] =
                make_uint2(*(unsigned*)&h01, *(unsigned*)&h23);
            float dv = dinv[grow];
            float s = dv * dv;
            float4 bv = ((const float4*)bias)[g];
            ((float4*)Yinit)[(size_t)grow * 32 + g] =
                make_float4(fmaf(v.x, s, bv.x), fmaf(v.y, s, bv.y),
                            fmaf(v.z, s, bv.z), fmaf(v.w, s, bv.w));
        }
    }
}

// ---------------- tc GEMM fout=48: fp32 X, writes h48 fp32 + d_out init ----------
__global__ void __launch_bounds__(256, 2)
k_gemm40_tc(const float* __restrict__ X, const __half* __restrict__ W,
            float* __restrict__ H48, const float* __restrict__ bias,
            const float* __restrict__ dinv, float* __restrict__ Out, int n) {
    extern __shared__ char smc[];
    __half* Ws = (__half*)smc;               // 12KB
    __half* Xs = (__half*)(smc + 12 * 1024); // 32KB
    int tid = threadIdx.x, wid = tid >> 5;
    int row0 = blockIdx.x * 128;

    for (int i = tid; i < NF * FO3P / 8; i += 256)
        ((uint4*)Ws)[i] = ((const uint4*)W)[i];
    for (int i = tid; i < 2048; i += 256) {   // 128 rows x 16 uint4
        int row = i >> 4, c = i & 15;
        uint4 v = make_uint4(0, 0, 0, 0);
        if (row0 + row < n) {
            const float4* xr = (const float4*)(X + (size_t)(row0 + row) * NF);
            float4 f0 = xr[c * 2], f1 = xr[c * 2 + 1];
            f0.x = fmaxf(f0.x, 0.f); f0.y = fmaxf(f0.y, 0.f);
            f0.z = fmaxf(f0.z, 0.f); f0.w = fmaxf(f0.w, 0.f);
            f1.x = fmaxf(f1.x, 0.f); f1.y = fmaxf(f1.y, 0.f);
            f1.z = fmaxf(f1.z, 0.f); f1.w = fmaxf(f1.w, 0.f);
            __half2 p0 = __floats2half2_rn(f0.x, f0.y);
            __half2 p1 = __floats2half2_rn(f0.z, f0.w);
            __half2 p2 = __floats2half2_rn(f1.x, f1.y);
            __half2 p3 = __floats2half2_rn(f1.z, f1.w);
            v = make_uint4(*(unsigned*)&p0, *(unsigned*)&p1,
                           *(unsigned*)&p2, *(unsigned*)&p3);
        }
        ((uint4*)Xs)[i] = v;
    }
    __syncthreads();

    wmma::fragment<wmma::accumulator, 16, 16, 16, float> c[3];
#pragma unroll
    for (int j = 0; j < 3; j++) wmma::fill_fragment(c[j], 0.f);

#pragma unroll
    for (int k0 = 0; k0 < NF; k0 += 16) {
        wmma::fragment<wmma::matrix_a, 16, 16, 16, __half, wmma::row_major> a;
        wmma::load_matrix_sync(a, Xs + wid * 16 * NF + k0, NF);
#pragma unroll
        for (int j = 0; j < 3; j++) {
            wmma::fragment<wmma::matrix_b, 16, 16, 16, __half, wmma::row_major> b;
            wmma::load_matrix_sync(b, Ws + k0 * FO3P + j * 16, FO3P);
            wmma::mma_sync(c[j], a, b, c[j]);
        }
    }
    __syncthreads();
    float* Cs = (float*)smc;
#pragma unroll
    for (int j = 0; j < 3; j++)
        wmma::store_matrix_sync(Cs + wid * 16 * FO3P + j * 16, c[j], FO3P,
                                wmma::mem_row_major);
    __syncthreads();

    for (int i = tid; i < 128 * 12; i += 256) {  // 12 float4 groups per row (48 f)
        int row = i / 12, g = i - row * 12;
        int grow = row0 + row;
        if (grow < n) {
            float4 v = ((const float4*)Cs)[i];
            ((float4*)(H48 + (size_t)grow * FO3P))[g] = v;
            if (g < 10) {  // 40 real cols = 10 float4
                float dv = dinv[grow];
                float s = dv * dv;
                float4 bv = ((const float4*)bias)[g];
                ((float4*)(Out + (size_t)grow * FO3))[g] =
                    make_float4(fmaf(v.x, s, bv.x), fmaf(v.y, s, bv.y),
                                fmaf(v.z, s, bv.z), fmaf(v.w, s, bv.w));
            }
        }
    }
}

// ---------------- edge-balanced aggregation, fp16 gather -> fp32 atomic out ------
__global__ void k_aggE128(const __half* __restrict__ h, float* __restrict__ out,
                          int nE) {
    int w = (blockIdx.x * blockDim.x + threadIdx.x) >> 5;
    int lane = threadIdx.x & 31;
    int e = w * 32;
    if (e >= nE) return;
    int e1 = min(e + 32, nE);
    int node = g_wstart[w];
    const uint2* h2 = (const uint2*)h;

    while (e < e1) {
        int nend = g_rowptr[node + 1];
        while (nend <= e) { node++; nend = g_rowptr[node + 1]; }
        int seg1 = nend < e1 ? nend : e1;
        float4 acc0 = make_float4(0.f, 0.f, 0.f, 0.f);
        float4 acc1 = make_float4(0.f, 0.f, 0.f, 0.f);
#define ACC_H(av, nbits, acc)                                             \
        {                                                                 \
            float nrm = __int_as_float(nbits);                            \
            float2 u = __half22float2(*(const __half2*)&(av).x);          \
            float2 v = __half22float2(*(const __half2*)&(av).y);          \
            acc.x = fmaf(u.x, nrm, acc.x); acc.y = fmaf(u.y, nrm, acc.y); \
            acc.z = fmaf(v.x, nrm, acc.z); acc.w = fmaf(v.y, nrm, acc.w); \
        }
        for (; e + 4 <= seg1; e += 4) {
            int2 q0 = g_epack[e],     q1 = g_epack[e + 1];
            int2 q2 = g_epack[e + 2], q3 = g_epack[e + 3];
            uint2 a0 = __ldg(&h2[(size_t)q0.x * 32 + lane]);
            uint2 a1 = __ldg(&h2[(size_t)q1.x * 32 + lane]);
            uint2 a2 = __ldg(&h2[(size_t)q2.x * 32 + lane]);
            uint2 a3 = __ldg(&h2[(size_t)q3.x * 32 + lane]);
            ACC_H(a0, q0.y, acc0) ACC_H(a1, q1.y, acc1)
            ACC_H(a2, q2.y, acc0) ACC_H(a3, q3.y, acc1)
        }
        for (; e < seg1; e++) {
            int2 q = g_epack[e];
            uint2 a = __ldg(&h2[(size_t)q.x * 32 + lane]);
            ACC_H(a, q.y, acc0)
        }
#undef ACC_H
        acc0.x += acc1.x; acc0.y += acc1.y; acc0.z += acc1.z; acc0.w += acc1.w;
        red4(out + (size_t)node * NF + lane * 4, acc0);
    }
}

// fout=40, fp32 gather (stride 48), atomic into d_out (stride 40), lanes<10
__global__ void k_aggE40(const float* __restrict__ h, float* __restrict__ out,
                         int nE) {
    int w = (blockIdx.x * blockDim.x + threadIdx.x) >> 5;
    int lane = threadIdx.x & 31;
    int e = w * 32;
    if (e >= nE || lane >= 10) return;
    int e1 = min(e + 32, nE);
    int node = g_wstart[w];

    while (e < e1) {
        int nend = g_rowptr[node + 1];
        while (nend <= e) { node++; nend = g_rowptr[node + 1]; }
        int seg1 = nend < e1 ? nend : e1;
        float4 acc0 = make_float4(0.f, 0.f, 0.f, 0.f);
        float4 acc1 = make_float4(0.f, 0.f, 0.f, 0.f);
        for (; e + 4 <= seg1; e += 4) {
            int2 q0 = g_epack[e],     q1 = g_epack[e + 1];
            int2 q2 = g_epack[e + 2], q3 = g_epack[e + 3];
            float4 a0 = __ldg((const float4*)(h + (size_t)q0.x * FO3P) + lane);
            float4 a1 = __ldg((const float4*)(h + (size_t)q1.x * FO3P) + lane);
            float4 a2 = __ldg((const float4*)(h + (size_t)q2.x * FO3P) + lane);
            float4 a3 = __ldg((const float4*)(h + (size_t)q3.x * FO3P) + lane);
            float n0 = __int_as_float(q0.y), n1 = __int_as_float(q1.y);
            float n2 = __int_as_float(q2.y), n3 = __int_as_float(q3.y);
            acc0.x = fmaf(a0.x, n0, acc0.x); acc0.y = fmaf(a0.y, n0, acc0.y);
            acc0.z = fmaf(a0.z, n0, acc0.z); acc0.w = fmaf(a0.w, n0, acc0.w);
            acc1.x = fmaf(a1.x, n1, acc1.x); acc1.y = fmaf(a1.y, n1, acc1.y);
            acc1.z = fmaf(a1.z, n1, acc1.z); acc1.w = fmaf(a1.w, n1, acc1.w);
            acc0.x = fmaf(a2.x, n2, acc0.x); acc0.y = fmaf(a2.y, n2, acc0.y);
            acc0.z = fmaf(a2.z, n2, acc0.z); acc0.w = fmaf(a2.w, n2, acc0.w);
            acc1.x = fmaf(a3.x, n3, acc1.x); acc1.y = fmaf(a3.y, n3, acc1.y);
            acc1.z = fmaf(a3.z, n3, acc1.z); acc1.w = fmaf(a3.w, n3, acc1.w);
        }
        for (; e < seg1; e++) {
            int2 q = g_epack[e];
            float4 a = __ldg((const float4*)(h + (size_t)q.x * FO3P) + lane);
            float nrm = __int_as_float(q.y);
            acc0.x = fmaf(a.x, nrm, acc0.x); acc0.y = fmaf(a.y, nrm, acc0.y);
            acc0.z = fmaf(a.z, nrm, acc0.z); acc0.w = fmaf(a.w, nrm, acc0.w);
        }
        acc0.x += acc1.x; acc0.y += acc1.y; acc0.z += acc1.z; acc0.w += acc1.w;
        red4(out + (size_t)node * FO3 + lane * 4, acc0);
    }
}

// ---------------- launch ----------------
extern "C" void kernel_launch(void* const* d_in, const int* in_sizes, int n_in,
                              void* d_out, int out_size) {
    const float* x  = (const float*)d_in[0];
    const void*  ei = d_in[1];
    const float* ew = (const float*)d_in[2];
    const float* W1 = (const float*)d_in[3];
    const float* b1 = (const float*)d_in[4];
    const float* W2 = (const float*)d_in[5];
    const float* b2 = (const float*)d_in[6];
    const float* W3 = (const float*)d_in[7];
    const float* b3 = (const float*)d_in[8];
    int n  = in_sizes[0] / NF;
    int nE = in_sizes[2];
    float* out = (float*)d_out;

    float *dinv, *h32, *y32;
    __half *hh, *w2h, *w3h;
    int *rowptr, *wstart, *cur, *cnt, *bsum;
    cudaGetSymbolAddress((void**)&dinv, g_deg);
    cudaGetSymbolAddress((void**)&hh, g_hh);
    cudaGetSymbolAddress((void**)&h32, g_h32);
    cudaGetSymbolAddress((void**)&y32, g_y32);
    cudaGetSymbolAddress((void**)&w2h, g_w2h);
    cudaGetSymbolAddress((void**)&w3h, g_w3h);
    cudaGetSymbolAddress((void**)&rowptr, g_rowptr);
    cudaGetSymbolAddress((void**)&wstart, g_wstart);
    cudaGetSymbolAddress((void**)&cur, g_cur);
    cudaGetSymbolAddress((void**)&cnt, g_cnt);
    cudaGetSymbolAddress((void**)&bsum, g_bsum);

    const int T = 256;
    size_t smemF32 = (size_t)(NF * NF + 8 * 8 * NF) * sizeof(float);
    size_t smemTC128 = 48 * 1024;
    size_t smemTC40  = 44 * 1024;
    cudaFuncSetAttribute(k_gemm128_f32, cudaFuncAttributeMaxDynamicSharedMemorySize, (int)smemF32);
    cudaFuncSetAttribute(k_gemm128_tc,  cudaFuncAttributeMaxDynamicSharedMemorySize, (int)smemTC128);
    cudaFuncSetAttribute(k_gemm40_tc,   cudaFuncAttributeMaxDynamicSharedMemorySize, (int)smemTC40);

    int gb64  = (n + 63) / 64;
    int gb128 = (n + 127) / 128;
    int nb = (n + 1023) / 1024;
    int nwarp = (nE + 31) / 32;
    int abE = (nwarp + 7) / 8;                 // 8 warp-chunks per 256-thr block
    long long tot1 = (long long)n * 32;

    cudaStream_t s2;
    cudaStreamCreateWithFlags(&s2, cudaStreamNonBlocking);
    cudaEvent_t evF, evJ;
    cudaEventCreateWithFlags(&evF, cudaEventDisableTiming);
    cudaEventCreateWithFlags(&evJ, cudaEventDisableTiming);

    cudaEventRecord(evF, 0);

    // Setup chain (6 kernels), overlapped with GEMM1 on s2
    k_init<<<(n + T - 1) / T, T>>>((const long long*)ei, nE, W2, W3, w2h, w3h,
                                   dinv, cnt, n);
    k_prep<<<(nE + T - 1) / T, T>>>(ei, ew, dinv, cnt, nE);
    k_scanA<<<nb, 1024>>>(cnt, rowptr, bsum, n);
    k_scanCB<<<(n + T - 1) / T, T>>>(rowptr, bsum, cur, dinv, n, nE, nb);
    k_place<<<(nE + T - 1) / T, T>>>(ew, dinv, nE);
    k_wstart<<<(nwarp + T - 1) / T, T>>>(rowptr, wstart, nwarp, n);

    cudaStreamWaitEvent(s2, evF, 0);
    k_gemm128_f32<<<gb64, T, smemF32, s2>>>(x, W1, hh, n);
    cudaEventRecord(evJ, s2);
    cudaStreamWaitEvent(0, evJ, 0);

    // Layer 1: y init (bias + self) then edge-balanced atomic aggregation
    k_init1<<<(int)((tot1 + T - 1) / T), T>>>(hh, b1, dinv, y32, tot1);
    k_aggE128<<<abE, T>>>(hh, y32, nE);
    // Layer 2: tc GEMM (fp32 in, ReLU fused; writes hh + y init), agg
    k_gemm128_tc<<<gb64, T, smemTC128>>>(y32, w2h, hh, b2, dinv, y32, n);
    k_aggE128<<<abE, T>>>(hh, y32, nE);
    // Layer 3: tc GEMM (writes h48 + d_out init), agg into d_out
    k_gemm40_tc<<<gb128, T, smemTC40>>>(y32, w3h, h32, b3, dinv, out, n);
    k_aggE40<<<abE, T>>>(h32, out, nE);
}

// round 11
// speedup vs baseline: 1.1412x; 1.1412x over previous
#include <cuda_runtime.h>
#include <cuda_fp16.h>
#include <mma.h>
#include <cstdint>

using namespace nvcuda;

#define NN 100000
#define NE_CAP 1600000
#define NF 128
#define FO3 40
#define FO3P 48

typedef unsigned long long u64;

// ---------------- device scratch ----------------
__device__ float  g_deg[NN];
__device__ __half g_hh[(size_t)NN * NF];
__device__ float  g_h32[(size_t)NN * NF];
__device__ __half g_yh[(size_t)NN * NF];
__device__ __half g_w2h[NF * NF];
__device__ __half g_w3h[NF * FO3P];
__device__ int2   g_sd[NE_CAP];
__device__ int2   g_epack[NE_CAP];
__device__ int    g_rowptr[NN + 1];
__device__ int    g_cur[NN];
__device__ int    g_cnt[NN];
__device__ int    g_bsum[128];
__device__ int    g_is32;

// ---------------- f32x2 helpers ----------------
__device__ __forceinline__ void ffma2(u64& d, u64 a, u64 b) {
    asm("fma.rn.f32x2 %0, %1, %2, %0;" : "+l"(d) : "l"(a), "l"(b));
}
__device__ __forceinline__ u64 dup2(float x) {
    u64 r; asm("mov.b64 %0, {%1, %1};" : "=l"(r) : "f"(x)); return r;
}
__device__ __forceinline__ float2 upk2(u64 v) {
    float2 r; asm("mov.b64 {%0, %1}, %2;" : "=f"(r.x), "=f"(r.y) : "l"(v)); return r;
}

// ---------------- fused init ----------------
__global__ void k_init(const long long* __restrict__ raw, int nE,
                       const float* __restrict__ W2, const float* __restrict__ W3,
                       __half* __restrict__ W2h, __half* __restrict__ W3h,
                       float* deg, int* cnt, int n) {
    int tid = threadIdx.x;
    int gid = blockIdx.x * blockDim.x + tid;
    int gsz = gridDim.x * blockDim.x;

    if (blockIdx.x == 0) {
        __shared__ int sflag;
        if (tid == 0) sflag = 0;
        __syncthreads();
        int lim = nE < 4096 ? nE : 4096;
        int bad = 0;
        for (int i = tid; i < lim; i += blockDim.x) {
            long long v = raw[i];
            if (v < 0 || v >= (1LL << 30)) bad = 1;
        }
        if (bad) atomicOr(&sflag, 1);
        __syncthreads();
        if (tid == 0) g_is32 = sflag;
    }

    for (int i = gid; i < n; i += gsz) { deg[i] = 0.f; cnt[i] = 0; }
    for (int i = gid; i < NF * NF; i += gsz) W2h[i] = __float2half(W2[i]);
    for (int i = gid; i < NF * FO3P; i += gsz) {
        int r = i / FO3P, c = i - r * FO3P;
        W3h[i] = (c < FO3) ? __float2half(W3[r * FO3 + c]) : __half(0);
    }
}

__global__ void k_prep(const void* __restrict__ raw, const float* __restrict__ ew,
                       float* deg, int* cnt, int nE) {
    int e = blockIdx.x * blockDim.x + threadIdx.x;
    if (e >= nE) return;
    int s, d;
    if (g_is32) {
        const int* p = (const int*)raw;
        s = p[e]; d = p[(size_t)nE + e];
    } else {
        const long long* p = (const long long*)raw;
        s = (int)p[e]; d = (int)p[(size_t)nE + e];
    }
    g_sd[e] = make_int2(s, d);
    atomicAdd(&deg[d], ew[e]);
    atomicAdd(&cnt[d], 1);
}

__global__ void k_scanA(const int* __restrict__ cnt, int* rowptr, int* bsum, int n) {
    __shared__ int s[1024];
    int t = threadIdx.x, i = blockIdx.x * 1024 + t;
    int v = (i < n) ? cnt[i] : 0;
    s[t] = v;
    __syncthreads();
#pragma unroll
    for (int off = 1; off < 1024; off <<= 1) {
        int x = (t >= off) ? s[t - off] : 0;
        __syncthreads();
        s[t] += x;
        __syncthreads();
    }
    if (i < n) rowptr[i] = s[t] - v;
    if (t == 1023) bsum[blockIdx.x] = s[1023];
}

__global__ void k_scanCB(int* rowptr, const int* __restrict__ bsum, int* cur,
                         float* deg, int n, int nE, int nb) {
    __shared__ int sb[128];
    int t = threadIdx.x;
    if (t < 128) sb[t] = (t < nb) ? bsum[t] : 0;
    __syncthreads();
#pragma unroll
    for (int off = 1; off < 128; off <<= 1) {
        int x = 0;
        if (t < 128 && t >= off) x = sb[t - off];
        __syncthreads();
        if (t < 128) sb[t] += x;
        __syncthreads();
    }
    int i = blockIdx.x * blockDim.x + t;
    if (i < n) {
        int j = i >> 10;
        int off = (j == 0) ? 0 : sb[j - 1];
        int v = rowptr[i] + off;
        rowptr[i] = v;
        cur[i] = v;
        deg[i] = rsqrtf(deg[i] + 1.0f);
    }
    if (i == 0) rowptr[n] = nE;
}

__global__ void k_place(const float* __restrict__ ew, const float* __restrict__ dinv,
                        int nE) {
    int e = blockIdx.x * blockDim.x + threadIdx.x;
    if (e >= nE) return;
    int2 sd = g_sd[e];
    int p = atomicAdd(&g_cur[sd.y], 1);
    float norm = ew[e] * dinv[sd.x] * dinv[sd.y];
    g_epack[p] = make_int2(sd.x, __float_as_int(norm));
}

// ---------------- layer-1 GEMM (fp32, FFMA2) -> fp16 ----------------
__global__ void __launch_bounds__(256, 2)
k_gemm128_f32(const float* __restrict__ X, const float* __restrict__ W,
              __half* __restrict__ Hh, int n) {
    extern __shared__ float sm[];
    float* Ws = sm;
    float* Xs = sm + NF * NF;
    int tid = threadIdx.x, warp = tid >> 5, lane = tid & 31;

    for (int i = tid; i < NF * NF / 4; i += 256)
        ((float4*)Ws)[i] = ((const float4*)W)[i];

    int row0 = blockIdx.x * 64 + warp * 8;
    float* xs = Xs + warp * (8 * NF);
#pragma unroll
    for (int r = 0; r < 8; r++) {
        int row = row0 + r;
        float4 v = make_float4(0.f, 0.f, 0.f, 0.f);
        if (row < n) v = ((const float4*)(X + (size_t)row * NF))[lane];
        ((float4*)(xs + r * NF))[lane] = v;
    }
    __syncthreads();

    u64 acc[8][2];
#pragma unroll
    for (int r = 0; r < 8; r++) { acc[r][0] = 0ull; acc[r][1] = 0ull; }

    const float* wl = Ws + 4 * lane;
    for (int k4 = 0; k4 < NF; k4 += 4) {
        float4 xv[8];
#pragma unroll
        for (int r = 0; r < 8; r++)
            xv[r] = *(const float4*)(xs + r * NF + k4);
#pragma unroll
        for (int kk = 0; kk < 4; kk++) {
            const float* wp = wl + (k4 + kk) * NF;
            u64 w01 = *(const u64*)(wp);
            u64 w23 = *(const u64*)(wp + 2);
#pragma unroll
            for (int r = 0; r < 8; r++) {
                float xk = kk == 0 ? xv[r].x : kk == 1 ? xv[r].y
                         : kk == 2 ? xv[r].z : xv[r].w;
                u64 xk2 = dup2(xk);
                ffma2(acc[r][0], xk2, w01);
                ffma2(acc[r][1], xk2, w23);
            }
        }
    }
#pragma unroll
    for (int r = 0; r < 8; r++) {
        int row = row0 + r;
        if (row < n) {
            float2 a = upk2(acc[r][0]), b = upk2(acc[r][1]);
            __half2 h01 = __floats2half2_rn(a.x, a.y);
            __half2 h23 = __floats2half2_rn(b.x, b.y);
            ((uint2*)(Hh + (size_t)row * NF))[lane] =
                make_uint2(*(unsigned*)&h01, *(unsigned*)&h23);
        }
    }
}

// ---------------- tc GEMM fout=128 ----------------
__global__ void __launch_bounds__(256, 2)
k_gemm128_tc(const __half* __restrict__ X, const __half* __restrict__ W,
             __half* __restrict__ Hh, int n) {
    extern __shared__ char smc[];
    __half* Ws = (__half*)smc;
    __half* Xs = (__half*)(smc + 32 * 1024);
    int tid = threadIdx.x, wid = tid >> 5;
    int warp_m = wid >> 1, warp_n = wid & 1;
    int row0 = blockIdx.x * 64;

    for (int i = tid; i < 2048; i += 256)
        ((uint4*)Ws)[i] = ((const uint4*)W)[i];
    __half2 z2 = __floats2half2_rn(0.f, 0.f);
    for (int i = tid; i < 1024; i += 256) {
        int row = i >> 4, c = i & 15;
        uint4 v = make_uint4(0, 0, 0, 0);
        if (row0 + row < n) {
            v = ((const uint4*)(X + (size_t)(row0 + row) * NF))[c];
            __half2* hv = (__half2*)&v;
            hv[0] = __hmax2(hv[0], z2); hv[1] = __hmax2(hv[1], z2);
            hv[2] = __hmax2(hv[2], z2); hv[3] = __hmax2(hv[3], z2);
        }
        ((uint4*)Xs)[i] = v;
    }
    __syncthreads();

    wmma::fragment<wmma::accumulator, 16, 16, 16, float> c[4];
#pragma unroll
    for (int j = 0; j < 4; j++) wmma::fill_fragment(c[j], 0.f);

#pragma unroll
    for (int k0 = 0; k0 < NF; k0 += 16) {
        wmma::fragment<wmma::matrix_a, 16, 16, 16, __half, wmma::row_major> a;
        wmma::load_matrix_sync(a, Xs + warp_m * 16 * NF + k0, NF);
#pragma unroll
        for (int j = 0; j < 4; j++) {
            wmma::fragment<wmma::matrix_b, 16, 16, 16, __half, wmma::row_major> b;
            wmma::load_matrix_sync(b, Ws + k0 * NF + warp_n * 64 + j * 16, NF);
            wmma::mma_sync(c[j], a, b, c[j]);
        }
    }
    __syncthreads();
    float* Cs = (float*)smc;
#pragma unroll
    for (int j = 0; j < 4; j++)
        wmma::store_matrix_sync(Cs + warp_m * 16 * NF + warp_n * 64 + j * 16,
                                c[j], NF, wmma::mem_row_major);
    __syncthreads();

    for (int i = tid; i < 64 * 32; i += 256) {
        int row = i >> 5, g = i & 31;
        if (row0 + row < n) {
            float4 v = ((const float4*)Cs)[i];
            __half2 h01 = __floats2half2_rn(v.x, v.y);
            __half2 h23 = __floats2half2_rn(v.z, v.w);
            ((uint2*)(Hh + (size_t)(row0 + row) * NF))[g] =
                make_uint2(*(unsigned*)&h01, *(unsigned*)&h23);
        }
    }
}

// ---------------- tc GEMM fout=48 ----------------
__global__ void __launch_bounds__(256, 2)
k_gemm40_tc(const __half* __restrict__ X, const __half* __restrict__ W,
            float* __restrict__ H, int n) {
    extern __shared__ char smc[];
    __half* Ws = (__half*)smc;
    __half* Xs = (__half*)(smc + 12 * 1024);
    int tid = threadIdx.x, wid = tid >> 5;
    int row0 = blockIdx.x * 128;

    for (int i = tid; i < NF * FO3P / 8; i += 256)
        ((uint4*)Ws)[i] = ((const uint4*)W)[i];
    __half2 z2 = __floats2half2_rn(0.f, 0.f);
    for (int i = tid; i < 2048; i += 256) {
        int row = i >> 4, c = i & 15;
        uint4 v = make_uint4(0, 0, 0, 0);
        if (row0 + row < n) {
            v = ((const uint4*)(X + (size_t)(row0 + row) * NF))[c];
            __half2* hv = (__half2*)&v;
            hv[0] = __hmax2(hv[0], z2); hv[1] = __hmax2(hv[1], z2);
            hv[2] = __hmax2(hv[2], z2); hv[3] = __hmax2(hv[3], z2);
        }
        ((uint4*)Xs)[i] = v;
    }
    __syncthreads();

    wmma::fragment<wmma::accumulator, 16, 16, 16, float> c[3];
#pragma unroll
    for (int j = 0; j < 3; j++) wmma::fill_fragment(c[j], 0.f);

#pragma unroll
    for (int k0 = 0; k0 < NF; k0 += 16) {
        wmma::fragment<wmma::matrix_a, 16, 16, 16, __half, wmma::row_major> a;
        wmma::load_matrix_sync(a, Xs + wid * 16 * NF + k0, NF);
#pragma unroll
        for (int j = 0; j < 3; j++) {
            wmma::fragment<wmma::matrix_b, 16, 16, 16, __half, wmma::row_major> b;
            wmma::load_matrix_sync(b, Ws + k0 * FO3P + j * 16, FO3P);
            wmma::mma_sync(c[j], a, b, c[j]);
        }
    }
    __syncthreads();
    float* Cs = (float*)smc;
#pragma unroll
    for (int j = 0; j < 3; j++)
        wmma::store_matrix_sync(Cs + wid * 16 * FO3P + j * 16, c[j], FO3P,
                                wmma::mem_row_major);
    __syncthreads();

    for (int i = tid; i < 128 * 24; i += 256) {
        int row = i / 24, g = i - row * 24;
        if (row0 + row < n)
            ((float2*)(H + (size_t)(row0 + row) * FO3P))[g] = ((const float2*)Cs)[i];
    }
}

// ---------------- agg fp16, warp-per-node (R9 form), 64-thread blocks ----------------
__device__ __forceinline__ void agg_edge_h(const uint2* h2, int src, float nrm,
                                           int lane, float4& acc) {
    uint2 a = __ldg(&h2[(size_t)src * 32 + lane]);
    float2 a01 = __half22float2(*(const __half2*)&a.x);
    float2 a23 = __half22float2(*(const __half2*)&a.y);
    acc.x = fmaf(a01.x, nrm, acc.x); acc.y = fmaf(a01.y, nrm, acc.y);
    acc.z = fmaf(a23.x, nrm, acc.z); acc.w = fmaf(a23.y, nrm, acc.w);
}

__global__ void k_agg128h(const __half* __restrict__ h, const float* __restrict__ bias,
                          const float* __restrict__ dinv, __half* __restrict__ outh,
                          int n) {
    int node = (blockIdx.x * blockDim.x + threadIdx.x) >> 5;
    int lane = threadIdx.x & 31;
    if (node >= n) return;
    const uint2* h2 = (const uint2*)h;
    float dv = dinv[node];
    float selfn = dv * dv;

    uint2 sp = __ldg(&h2[(size_t)node * 32 + lane]);
    float2 s01 = __half22float2(*(const __half2*)&sp.x);
    float2 s23 = __half22float2(*(const __half2*)&sp.y);
    float4 acc0 = make_float4(s01.x * selfn, s01.y * selfn,
                              s23.x * selfn, s23.y * selfn);
    float4 acc1 = make_float4(0.f, 0.f, 0.f, 0.f);

    int p = g_rowptr[node], p1 = g_rowptr[node + 1];
    if ((p & 1) && p < p1) {
        int2 e = g_epack[p];
        agg_edge_h(h2, e.x, __int_as_float(e.y), lane, acc0);
        p++;
    }
    const int4* ep4 = (const int4*)g_epack;
    for (; p + 8 <= p1; p += 8) {
        int h0 = p >> 1;
        int4 q0 = ep4[h0], q1 = ep4[h0 + 1], q2 = ep4[h0 + 2], q3 = ep4[h0 + 3];
        uint2 a0 = __ldg(&h2[(size_t)q0.x * 32 + lane]);
        uint2 a1 = __ldg(&h2[(size_t)q0.z * 32 + lane]);
        uint2 a2 = __ldg(&h2[(size_t)q1.x * 32 + lane]);
        uint2 a3 = __ldg(&h2[(size_t)q1.z * 32 + lane]);
        uint2 a4 = __ldg(&h2[(size_t)q2.x * 32 + lane]);
        uint2 a5 = __ldg(&h2[(size_t)q2.z * 32 + lane]);
        uint2 a6 = __ldg(&h2[(size_t)q3.x * 32 + lane]);
        uint2 a7 = __ldg(&h2[(size_t)q3.z * 32 + lane]);
#define ACC_H(av, nbits, acc)                                           \
        {                                                               \
            float nrm = __int_as_float(nbits);                          \
            float2 u = __half22float2(*(const __half2*)&(av).x);        \
            float2 w = __half22float2(*(const __half2*)&(av).y);        \
            acc.x = fmaf(u.x, nrm, acc.x); acc.y = fmaf(u.y, nrm, acc.y); \
            acc.z = fmaf(w.x, nrm, acc.z); acc.w = fmaf(w.y, nrm, acc.w); \
        }
        ACC_H(a0, q0.y, acc0) ACC_H(a1, q0.w, acc1)
        ACC_H(a2, q1.y, acc0) ACC_H(a3, q1.w, acc1)
        ACC_H(a4, q2.y, acc0) ACC_H(a5, q2.w, acc1)
        ACC_H(a6, q3.y, acc0) ACC_H(a7, q3.w, acc1)
#undef ACC_H
    }
    for (; p < p1; p++) {
        int2 e = g_epack[p];
        agg_edge_h(h2, e.x, __int_as_float(e.y), lane, acc0);
    }
    float4 bv = ((const float4*)bias)[lane];
    acc0.x += acc1.x + bv.x; acc0.y += acc1.y + bv.y;
    acc0.z += acc1.z + bv.z; acc0.w += acc1.w + bv.w;
    __half2 o01 = __floats2half2_rn(acc0.x, acc0.y);
    __half2 o23 = __floats2half2_rn(acc0.z, acc0.w);
    ((uint2*)outh)[(size_t)node * 32 + lane] =
        make_uint2(*(unsigned*)&o01, *(unsigned*)&o23);
}

// ---------------- agg fp32 fout=40 (padded 48 input) ----------------
__global__ void k_agg40(const float* __restrict__ h, const float* __restrict__ bias,
                        const float* __restrict__ dinv, float* __restrict__ out,
                        int n) {
    int node = (blockIdx.x * blockDim.x + threadIdx.x) >> 5;
    int lane = threadIdx.x & 31;
    if (node >= n || lane >= 20) return;
    float dv = dinv[node];
    float selfn = dv * dv;
    float2 sv = __ldg((const float2*)(h + (size_t)node * FO3P) + lane);
    float2 acc0 = make_float2(sv.x * selfn, sv.y * selfn);
    float2 acc1 = make_float2(0.f, 0.f);

    int p = g_rowptr[node], p1 = g_rowptr[node + 1];
    if ((p & 1) && p < p1) {
        int2 e = g_epack[p];
        float2 a = __ldg((const float2*)(h + (size_t)e.x * FO3P) + lane);
        float nrm = __int_as_float(e.y);
        acc0.x = fmaf(a.x, nrm, acc0.x); acc0.y = fmaf(a.y, nrm, acc0.y);
        p++;
    }
    const int4* ep4 = (const int4*)g_epack;
    for (; p + 8 <= p1; p += 8) {
        int h0 = p >> 1;
        int4 q0 = ep4[h0], q1 = ep4[h0 + 1], q2 = ep4[h0 + 2], q3 = ep4[h0 + 3];
        float2 a0 = __ldg((const float2*)(h + (size_t)q0.x * FO3P) + lane);
        float2 a1 = __ldg((const float2*)(h + (size_t)q0.z * FO3P) + lane);
        float2 a2 = __ldg((const float2*)(h + (size_t)q1.x * FO3P) + lane);
        float2 a3 = __ldg((const float2*)(h + (size_t)q1.z * FO3P) + lane);
        float2 a4 = __ldg((const float2*)(h + (size_t)q2.x * FO3P) + lane);
        float2 a5 = __ldg((const float2*)(h + (size_t)q2.z * FO3P) + lane);
        float2 a6 = __ldg((const float2*)(h + (size_t)q3.x * FO3P) + lane);
        float2 a7 = __ldg((const float2*)(h + (size_t)q3.z * FO3P) + lane);
        float n0 = __int_as_float(q0.y), n1 = __int_as_float(q0.w);
        float n2 = __int_as_float(q1.y), n3 = __int_as_float(q1.w);
        float n4 = __int_as_float(q2.y), n5 = __int_as_float(q2.w);
        float n6 = __int_as_float(q3.y), n7 = __int_as_float(q3.w);
        acc0.x = fmaf(a0.x, n0, acc0.x); acc0.y = fmaf(a0.y, n0, acc0.y);
        acc1.x = fmaf(a1.x, n1, acc1.x); acc1.y = fmaf(a1.y, n1, acc1.y);
        acc0.x = fmaf(a2.x, n2, acc0.x); acc0.y = fmaf(a2.y, n2, acc0.y);
        acc1.x = fmaf(a3.x, n3, acc1.x); acc1.y = fmaf(a3.y, n3, acc1.y);
        acc0.x = fmaf(a4.x, n4, acc0.x); acc0.y = fmaf(a4.y, n4, acc0.y);
        acc1.x = fmaf(a5.x, n5, acc1.x); acc1.y = fmaf(a5.y, n5, acc1.y);
        acc0.x = fmaf(a6.x, n6, acc0.x); acc0.y = fmaf(a6.y, n6, acc0.y);
        acc1.x = fmaf(a7.x, n7, acc1.x); acc1.y = fmaf(a7.y, n7, acc1.y);
    }
    for (; p < p1; p++) {
        int2 e = g_epack[p];
        float2 a = __ldg((const float2*)(h + (size_t)e.x * FO3P) + lane);
        float nrm = __int_as_float(e.y);
        acc0.x = fmaf(a.x, nrm, acc0.x); acc0.y = fmaf(a.y, nrm, acc0.y);
    }
    float2 bv = ((const float2*)bias)[lane];
    acc0.x += acc1.x + bv.x; acc0.y += acc1.y + bv.y;
    ((float2*)(out + (size_t)node * FO3))[lane] = acc0;
}

// ---------------- launch ----------------
extern "C" void kernel_launch(void* const* d_in, const int* in_sizes, int n_in,
                              void* d_out, int out_size) {
    const float* x  = (const float*)d_in[0];
    const void*  ei = d_in[1];
    const float* ew = (const float*)d_in[2];
    const float* W1 = (const float*)d_in[3];
    const float* b1 = (const float*)d_in[4];
    const float* W2 = (const float*)d_in[5];
    const float* b2 = (const float*)d_in[6];
    const float* W3 = (const float*)d_in[7];
    const float* b3 = (const float*)d_in[8];
    int n  = in_sizes[0] / NF;
    int nE = in_sizes[2];
    float* out = (float*)d_out;

    float *dinv, *h32;
    __half *hh, *yh, *w2h, *w3h;
    int *rowptr, *cur, *cnt, *bsum;
    cudaGetSymbolAddress((void**)&dinv, g_deg);
    cudaGetSymbolAddress((void**)&hh, g_hh);
    cudaGetSymbolAddress((void**)&h32, g_h32);
    cudaGetSymbolAddress((void**)&yh, g_yh);
    cudaGetSymbolAddress((void**)&w2h, g_w2h);
    cudaGetSymbolAddress((void**)&w3h, g_w3h);
    cudaGetSymbolAddress((void**)&rowptr, g_rowptr);
    cudaGetSymbolAddress((void**)&cur, g_cur);
    cudaGetSymbolAddress((void**)&cnt, g_cnt);
    cudaGetSymbolAddress((void**)&bsum, g_bsum);

    const int T = 256;
    const int TA = 64;   // agg blocks: 2 warps -> minimal straggler coupling
    size_t smemF32 = (size_t)(NF * NF + 8 * 8 * NF) * sizeof(float);
    size_t smemTC128 = 48 * 1024;
    size_t smemTC40  = 44 * 1024;
    cudaFuncSetAttribute(k_gemm128_f32, cudaFuncAttributeMaxDynamicSharedMemorySize, (int)smemF32);
    cudaFuncSetAttribute(k_gemm128_tc,  cudaFuncAttributeMaxDynamicSharedMemorySize, (int)smemTC128);
    cudaFuncSetAttribute(k_gemm40_tc,   cudaFuncAttributeMaxDynamicSharedMemorySize, (int)smemTC40);

    int gb64  = (n + 63) / 64;
    int gb128 = (n + 127) / 128;
    int ab = (n * 32 + TA - 1) / TA;   // 2 nodes (warps) per 64-thread block
    int nb = (n + 1023) / 1024;

    cudaStream_t s2;
    cudaStreamCreateWithFlags(&s2, cudaStreamNonBlocking);
    cudaEvent_t evF, evJ;
    cudaEventCreateWithFlags(&evF, cudaEventDisableTiming);
    cudaEventCreateWithFlags(&evJ, cudaEventDisableTiming);

    cudaEventRecord(evF, 0);

    // Setup chain (5 kernels)
    k_init<<<(n + T - 1) / T, T>>>((const long long*)ei, nE, W2, W3, w2h, w3h,
                                   dinv, cnt, n);
    k_prep<<<(nE + T - 1) / T, T>>>(ei, ew, dinv, cnt, nE);
    k_scanA<<<nb, 1024>>>(cnt, rowptr, bsum, n);
    k_scanCB<<<(n + T - 1) / T, T>>>(rowptr, bsum, cur, dinv, n, nE, nb);
    k_place<<<(nE + T - 1) / T, T>>>(ew, dinv, nE);

    // Fork branch: GEMM1 overlaps the setup chain at replay
    cudaStreamWaitEvent(s2, evF, 0);
    k_gemm128_f32<<<gb64, T, smemF32, s2>>>(x, W1, hh, n);
    cudaEventRecord(evJ, s2);
    cudaStreamWaitEvent(0, evJ, 0);

    // Layer 1 agg
    k_agg128h<<<ab, TA>>>(hh, b1, dinv, yh, n);
    // Layer 2
    k_gemm128_tc<<<gb64, T, smemTC128>>>(yh, w2h, hh, n);
    k_agg128h<<<ab, TA>>>(hh, b2, dinv, yh, n);
    // Layer 3
    k_gemm40_tc<<<gb128, T, smemTC40>>>(yh, w3h, h32, n);
    k_agg40<<<ab, TA>>>(h32, b3, dinv, out, n);
}

// round 12
// speedup vs baseline: 1.1542x; 1.0114x over previous
#include <cuda_runtime.h>
#include <cuda_fp16.h>
#include <mma.h>
#include <cstdint>

using namespace nvcuda;

#define NN 100000
#define NE_CAP 1600000
#define NF 128
#define FO3 40
#define FO3P 48

typedef unsigned long long u64;

// ---------------- device scratch ----------------
__device__ float  g_deg[NN];
__device__ __half g_hh[(size_t)NN * NF];
__device__ float  g_h32[(size_t)NN * NF];
__device__ __half g_yh[(size_t)NN * NF];
__device__ __half g_w2h[NF * NF];
__device__ __half g_w3h[NF * FO3P];
__device__ int2   g_sd[NE_CAP];
__device__ int2   g_epack[NE_CAP];
__device__ int    g_rowptr[NN + 1];
__device__ int    g_cur[NN];
__device__ int    g_cnt[NN];
__device__ int    g_bsum[128];
__device__ int    g_is32;

// ---------------- f32x2 helpers ----------------
__device__ __forceinline__ void ffma2(u64& d, u64 a, u64 b) {
    asm("fma.rn.f32x2 %0, %1, %2, %0;" : "+l"(d) : "l"(a), "l"(b));
}
__device__ __forceinline__ u64 dup2(float x) {
    u64 r; asm("mov.b64 %0, {%1, %1};" : "=l"(r) : "f"(x)); return r;
}
__device__ __forceinline__ float2 upk2(u64 v) {
    float2 r; asm("mov.b64 {%0, %1}, %2;" : "=f"(r.x), "=f"(r.y) : "l"(v)); return r;
}

// ---------------- fused init ----------------
__global__ void k_init(const long long* __restrict__ raw, int nE,
                       const float* __restrict__ W2, const float* __restrict__ W3,
                       __half* __restrict__ W2h, __half* __restrict__ W3h,
                       float* deg, int* cnt, int n) {
    int tid = threadIdx.x;
    int gid = blockIdx.x * blockDim.x + tid;
    int gsz = gridDim.x * blockDim.x;

    if (blockIdx.x == 0) {
        __shared__ int sflag;
        if (tid == 0) sflag = 0;
        __syncthreads();
        int lim = nE < 4096 ? nE : 4096;
        int bad = 0;
        for (int i = tid; i < lim; i += blockDim.x) {
            long long v = raw[i];
            if (v < 0 || v >= (1LL << 30)) bad = 1;
        }
        if (bad) atomicOr(&sflag, 1);
        __syncthreads();
        if (tid == 0) g_is32 = sflag;
    }

    for (int i = gid; i < n; i += gsz) { deg[i] = 0.f; cnt[i] = 0; }
    for (int i = gid; i < NF * NF; i += gsz) W2h[i] = __float2half(W2[i]);
    for (int i = gid; i < NF * FO3P; i += gsz) {
        int r = i / FO3P, c = i - r * FO3P;
        W3h[i] = (c < FO3) ? __float2half(W3[r * FO3 + c]) : __half(0);
    }
}

__global__ void k_prep(const void* __restrict__ raw, const float* __restrict__ ew,
                       float* deg, int* cnt, int nE) {
    int e = blockIdx.x * blockDim.x + threadIdx.x;
    if (e >= nE) return;
    int s, d;
    if (g_is32) {
        const int* p = (const int*)raw;
        s = p[e]; d = p[(size_t)nE + e];
    } else {
        const long long* p = (const long long*)raw;
        s = (int)p[e]; d = (int)p[(size_t)nE + e];
    }
    g_sd[e] = make_int2(s, d);
    atomicAdd(&deg[d], ew[e]);
    atomicAdd(&cnt[d], 1);
}

__global__ void k_scanA(const int* __restrict__ cnt, int* rowptr, int* bsum, int n) {
    __shared__ int s[1024];
    int t = threadIdx.x, i = blockIdx.x * 1024 + t;
    int v = (i < n) ? cnt[i] : 0;
    s[t] = v;
    __syncthreads();
#pragma unroll
    for (int off = 1; off < 1024; off <<= 1) {
        int x = (t >= off) ? s[t - off] : 0;
        __syncthreads();
        s[t] += x;
        __syncthreads();
    }
    if (i < n) rowptr[i] = s[t] - v;
    if (t == 1023) bsum[blockIdx.x] = s[1023];
}

__global__ void k_scanCB(int* rowptr, const int* __restrict__ bsum, int* cur,
                         float* deg, int n, int nE, int nb) {
    __shared__ int sb[128];
    int t = threadIdx.x;
    if (t < 128) sb[t] = (t < nb) ? bsum[t] : 0;
    __syncthreads();
#pragma unroll
    for (int off = 1; off < 128; off <<= 1) {
        int x = 0;
        if (t < 128 && t >= off) x = sb[t - off];
        __syncthreads();
        if (t < 128) sb[t] += x;
        __syncthreads();
    }
    int i = blockIdx.x * blockDim.x + t;
    if (i < n) {
        int j = i >> 10;
        int off = (j == 0) ? 0 : sb[j - 1];
        int v = rowptr[i] + off;
        rowptr[i] = v;
        cur[i] = v;
        deg[i] = rsqrtf(deg[i] + 1.0f);
    }
    if (i == 0) rowptr[n] = nE;
}

__global__ void k_place(const float* __restrict__ ew, const float* __restrict__ dinv,
                        int nE) {
    int e = blockIdx.x * blockDim.x + threadIdx.x;
    if (e >= nE) return;
    int2 sd = g_sd[e];
    int p = atomicAdd(&g_cur[sd.y], 1);
    float norm = ew[e] * dinv[sd.x] * dinv[sd.y];
    g_epack[p] = make_int2(sd.x, __float_as_int(norm));
}

// ---------------- layer-1 GEMM (fp32, FFMA2) -> fp16 ----------------
__global__ void __launch_bounds__(256, 2)
k_gemm128_f32(const float* __restrict__ X, const float* __restrict__ W,
              __half* __restrict__ Hh, int n) {
    extern __shared__ float sm[];
    float* Ws = sm;
    float* Xs = sm + NF * NF;
    int tid = threadIdx.x, warp = tid >> 5, lane = tid & 31;

    for (int i = tid; i < NF * NF / 4; i += 256)
        ((float4*)Ws)[i] = ((const float4*)W)[i];

    int row0 = blockIdx.x * 64 + warp * 8;
    float* xs = Xs + warp * (8 * NF);
#pragma unroll
    for (int r = 0; r < 8; r++) {
        int row = row0 + r;
        float4 v = make_float4(0.f, 0.f, 0.f, 0.f);
        if (row < n) v = ((const float4*)(X + (size_t)row * NF))[lane];
        ((float4*)(xs + r * NF))[lane] = v;
    }
    __syncthreads();

    u64 acc[8][2];
#pragma unroll
    for (int r = 0; r < 8; r++) { acc[r][0] = 0ull; acc[r][1] = 0ull; }

    const float* wl = Ws + 4 * lane;
    for (int k4 = 0; k4 < NF; k4 += 4) {
        float4 xv[8];
#pragma unroll
        for (int r = 0; r < 8; r++)
            xv[r] = *(const float4*)(xs + r * NF + k4);
#pragma unroll
        for (int kk = 0; kk < 4; kk++) {
            const float* wp = wl + (k4 + kk) * NF;
            u64 w01 = *(const u64*)(wp);
            u64 w23 = *(const u64*)(wp + 2);
#pragma unroll
            for (int r = 0; r < 8; r++) {
                float xk = kk == 0 ? xv[r].x : kk == 1 ? xv[r].y
                         : kk == 2 ? xv[r].z : xv[r].w;
                u64 xk2 = dup2(xk);
                ffma2(acc[r][0], xk2, w01);
                ffma2(acc[r][1], xk2, w23);
            }
        }
    }
#pragma unroll
    for (int r = 0; r < 8; r++) {
        int row = row0 + r;
        if (row < n) {
            float2 a = upk2(acc[r][0]), b = upk2(acc[r][1]);
            __half2 h01 = __floats2half2_rn(a.x, a.y);
            __half2 h23 = __floats2half2_rn(b.x, b.y);
            ((uint2*)(Hh + (size_t)row * NF))[lane] =
                make_uint2(*(unsigned*)&h01, *(unsigned*)&h23);
        }
    }
}

// ---------------- tc GEMM fout=128 ----------------
__global__ void __launch_bounds__(256, 2)
k_gemm128_tc(const __half* __restrict__ X, const __half* __restrict__ W,
             __half* __restrict__ Hh, int n) {
    extern __shared__ char smc[];
    __half* Ws = (__half*)smc;
    __half* Xs = (__half*)(smc + 32 * 1024);
    int tid = threadIdx.x, wid = tid >> 5;
    int warp_m = wid >> 1, warp_n = wid & 1;
    int row0 = blockIdx.x * 64;

    for (int i = tid; i < 2048; i += 256)
        ((uint4*)Ws)[i] = ((const uint4*)W)[i];
    __half2 z2 = __floats2half2_rn(0.f, 0.f);
    for (int i = tid; i < 1024; i += 256) {
        int row = i >> 4, c = i & 15;
        uint4 v = make_uint4(0, 0, 0, 0);
        if (row0 + row < n) {
            v = ((const uint4*)(X + (size_t)(row0 + row) * NF))[c];
            __half2* hv = (__half2*)&v;
            hv[0] = __hmax2(hv[0], z2); hv[1] = __hmax2(hv[1], z2);
            hv[2] = __hmax2(hv[2], z2); hv[3] = __hmax2(hv[3], z2);
        }
        ((uint4*)Xs)[i] = v;
    }
    __syncthreads();

    wmma::fragment<wmma::accumulator, 16, 16, 16, float> c[4];
#pragma unroll
    for (int j = 0; j < 4; j++) wmma::fill_fragment(c[j], 0.f);

#pragma unroll
    for (int k0 = 0; k0 < NF; k0 += 16) {
        wmma::fragment<wmma::matrix_a, 16, 16, 16, __half, wmma::row_major> a;
        wmma::load_matrix_sync(a, Xs + warp_m * 16 * NF + k0, NF);
#pragma unroll
        for (int j = 0; j < 4; j++) {
            wmma::fragment<wmma::matrix_b, 16, 16, 16, __half, wmma::row_major> b;
            wmma::load_matrix_sync(b, Ws + k0 * NF + warp_n * 64 + j * 16, NF);
            wmma::mma_sync(c[j], a, b, c[j]);
        }
    }
    __syncthreads();
    float* Cs = (float*)smc;
#pragma unroll
    for (int j = 0; j < 4; j++)
        wmma::store_matrix_sync(Cs + warp_m * 16 * NF + warp_n * 64 + j * 16,
                                c[j], NF, wmma::mem_row_major);
    __syncthreads();

    for (int i = tid; i < 64 * 32; i += 256) {
        int row = i >> 5, g = i & 31;
        if (row0 + row < n) {
            float4 v = ((const float4*)Cs)[i];
            __half2 h01 = __floats2half2_rn(v.x, v.y);
            __half2 h23 = __floats2half2_rn(v.z, v.w);
            ((uint2*)(Hh + (size_t)(row0 + row) * NF))[g] =
                make_uint2(*(unsigned*)&h01, *(unsigned*)&h23);
        }
    }
}

// ---------------- tc GEMM fout=48 ----------------
__global__ void __launch_bounds__(256, 2)
k_gemm40_tc(const __half* __restrict__ X, const __half* __restrict__ W,
            float* __restrict__ H, int n) {
    extern __shared__ char smc[];
    __half* Ws = (__half*)smc;
    __half* Xs = (__half*)(smc + 12 * 1024);
    int tid = threadIdx.x, wid = tid >> 5;
    int row0 = blockIdx.x * 128;

    for (int i = tid; i < NF * FO3P / 8; i += 256)
        ((uint4*)Ws)[i] = ((const uint4*)W)[i];
    __half2 z2 = __floats2half2_rn(0.f, 0.f);
    for (int i = tid; i < 2048; i += 256) {
        int row = i >> 4, c = i & 15;
        uint4 v = make_uint4(0, 0, 0, 0);
        if (row0 + row < n) {
            v = ((const uint4*)(X + (size_t)(row0 + row) * NF))[c];
            __half2* hv = (__half2*)&v;
            hv[0] = __hmax2(hv[0], z2); hv[1] = __hmax2(hv[1], z2);
            hv[2] = __hmax2(hv[2], z2); hv[3] = __hmax2(hv[3], z2);
        }
        ((uint4*)Xs)[i] = v;
    }
    __syncthreads();

    wmma::fragment<wmma::accumulator, 16, 16, 16, float> c[3];
#pragma unroll
    for (int j = 0; j < 3; j++) wmma::fill_fragment(c[j], 0.f);

#pragma unroll
    for (int k0 = 0; k0 < NF; k0 += 16) {
        wmma::fragment<wmma::matrix_a, 16, 16, 16, __half, wmma::row_major> a;
        wmma::load_matrix_sync(a, Xs + wid * 16 * NF + k0, NF);
#pragma unroll
        for (int j = 0; j < 3; j++) {
            wmma::fragment<wmma::matrix_b, 16, 16, 16, __half, wmma::row_major> b;
            wmma::load_matrix_sync(b, Ws + k0 * FO3P + j * 16, FO3P);
            wmma::mma_sync(c[j], a, b, c[j]);
        }
    }
    __syncthreads();
    float* Cs = (float*)smc;
#pragma unroll
    for (int j = 0; j < 3; j++)
        wmma::store_matrix_sync(Cs + wid * 16 * FO3P + j * 16, c[j], FO3P,
                                wmma::mem_row_major);
    __syncthreads();

    for (int i = tid; i < 128 * 24; i += 256) {
        int row = i / 24, g = i - row * 24;
        if (row0 + row < n)
            ((float2*)(H + (size_t)(row0 + row) * FO3P))[g] = ((const float2*)Cs)[i];
    }
}

// ---------------- agg fp16, half-warp-per-edge (lane=uint4, 8 cols) ----------------
// Warp per node; halves 0/1 process edges p and p+1 concurrently with LDG.128.
#define ACC8H(av, nrm)                                                     \
    {                                                                      \
        float2 u0 = __half22float2(*(const __half2*)&(av).x);              \
        float2 u1 = __half22float2(*(const __half2*)&(av).y);              \
        float2 u2 = __half22float2(*(const __half2*)&(av).z);              \
        float2 u3 = __half22float2(*(const __half2*)&(av).w);              \
        acc0.x = fmaf(u0.x, nrm, acc0.x); acc0.y = fmaf(u0.y, nrm, acc0.y);\
        acc0.z = fmaf(u1.x, nrm, acc0.z); acc0.w = fmaf(u1.y, nrm, acc0.w);\
        acc1.x = fmaf(u2.x, nrm, acc1.x); acc1.y = fmaf(u2.y, nrm, acc1.y);\
        acc1.z = fmaf(u3.x, nrm, acc1.z); acc1.w = fmaf(u3.y, nrm, acc1.w);\
    }

__global__ void k_agg128h(const __half* __restrict__ h, const float* __restrict__ bias,
                          const float* __restrict__ dinv, __half* __restrict__ outh,
                          int n) {
    int node = (blockIdx.x * blockDim.x + threadIdx.x) >> 5;
    int lane = threadIdx.x & 31;
    if (node >= n) return;
    int half = lane >> 4, sub = lane & 15;
    const uint4* h4 = (const uint4*)h;  // 16 uint4 per 128-col row
    float dv = dinv[node];
    float selfn = half ? 0.f : dv * dv;

    uint4 sp = __ldg(&h4[(size_t)node * 16 + sub]);
    float4 acc0 = make_float4(0.f, 0.f, 0.f, 0.f);
    float4 acc1 = make_float4(0.f, 0.f, 0.f, 0.f);
    ACC8H(sp, selfn)

    int p = g_rowptr[node], p1 = g_rowptr[node + 1];
    // peel to even p (single edge: half 1 contributes 0)
    if ((p & 1) && p < p1) {
        int2 e = g_epack[p];
        float nrm = half ? 0.f : __int_as_float(e.y);
        uint4 a = __ldg(&h4[(size_t)e.x * 16 + sub]);
        ACC8H(a, nrm)
        p++;
    }
    const int4* ep4 = (const int4*)g_epack;
    for (; p + 4 <= p1; p += 4) {
        int4 q0 = ep4[p >> 1], q1 = ep4[(p >> 1) + 1];
        int s0 = half ? q0.z : q0.x;
        int s1 = half ? q1.z : q1.x;
        float n0 = __int_as_float(half ? q0.w : q0.y);
        float n1 = __int_as_float(half ? q1.w : q1.y);
        uint4 a0 = __ldg(&h4[(size_t)s0 * 16 + sub]);
        uint4 a1 = __ldg(&h4[(size_t)s1 * 16 + sub]);
        ACC8H(a0, n0)
        ACC8H(a1, n1)
    }
    if (p + 2 <= p1) {
        int4 q = ep4[p >> 1];
        int s = half ? q.z : q.x;
        float nrm = __int_as_float(half ? q.w : q.y);
        uint4 a = __ldg(&h4[(size_t)s * 16 + sub]);
        ACC8H(a, nrm)
        p += 2;
    }
    if (p < p1) {
        int2 e = g_epack[p];
        float nrm = half ? 0.f : __int_as_float(e.y);
        uint4 a = __ldg(&h4[(size_t)e.x * 16 + sub]);
        ACC8H(a, nrm)
    }

    // combine halves (lane l += lane l+16)
    acc0.x += __shfl_down_sync(0xffffffffu, acc0.x, 16);
    acc0.y += __shfl_down_sync(0xffffffffu, acc0.y, 16);
    acc0.z += __shfl_down_sync(0xffffffffu, acc0.z, 16);
    acc0.w += __shfl_down_sync(0xffffffffu, acc0.w, 16);
    acc1.x += __shfl_down_sync(0xffffffffu, acc1.x, 16);
    acc1.y += __shfl_down_sync(0xffffffffu, acc1.y, 16);
    acc1.z += __shfl_down_sync(0xffffffffu, acc1.z, 16);
    acc1.w += __shfl_down_sync(0xffffffffu, acc1.w, 16);

    if (half == 0) {
        float4 b0 = ((const float4*)bias)[2 * sub];
        float4 b1 = ((const float4*)bias)[2 * sub + 1];
        acc0.x += b0.x; acc0.y += b0.y; acc0.z += b0.z; acc0.w += b0.w;
        acc1.x += b1.x; acc1.y += b1.y; acc1.z += b1.z; acc1.w += b1.w;
        __half2 o0 = __floats2half2_rn(acc0.x, acc0.y);
        __half2 o1 = __floats2half2_rn(acc0.z, acc0.w);
        __half2 o2 = __floats2half2_rn(acc1.x, acc1.y);
        __half2 o3 = __floats2half2_rn(acc1.z, acc1.w);
        ((uint4*)outh)[(size_t)node * 16 + sub] =
            make_uint4(*(unsigned*)&o0, *(unsigned*)&o1,
                       *(unsigned*)&o2, *(unsigned*)&o3);
    }
}

// ---------------- agg fp32 fout=40 (stride-48 in), half-warp-per-edge ----------------
__global__ void k_agg40(const float* __restrict__ h, const float* __restrict__ bias,
                        const float* __restrict__ dinv, float* __restrict__ out,
                        int n) {
    int node = (blockIdx.x * blockDim.x + threadIdx.x) >> 5;
    int lane = threadIdx.x & 31;
    if (node >= n) return;
    int half = lane >> 4, sub = lane & 15;
    if (sub >= 10) return;                 // 10 float4 = 40 cols
    const unsigned MASK = 0x03FF03FFu;     // lanes 0-9 and 16-25
    float dv = dinv[node];
    float selfn = half ? 0.f : dv * dv;

    float4 sp = __ldg((const float4*)(h + (size_t)node * FO3P) + sub);
    float4 acc = make_float4(sp.x * selfn, sp.y * selfn, sp.z * selfn, sp.w * selfn);

    int p = g_rowptr[node], p1 = g_rowptr[node + 1];
    if ((p & 1) && p < p1) {
        int2 e = g_epack[p];
        float nrm = half ? 0.f : __int_as_float(e.y);
        float4 a = __ldg((const float4*)(h + (size_t)e.x * FO3P) + sub);
        acc.x = fmaf(a.x, nrm, acc.x); acc.y = fmaf(a.y, nrm, acc.y);
        acc.z = fmaf(a.z, nrm, acc.z); acc.w = fmaf(a.w, nrm, acc.w);
        p++;
    }
    const int4* ep4 = (const int4*)g_epack;
    for (; p + 4 <= p1; p += 4) {
        int4 q0 = ep4[p >> 1], q1 = ep4[(p >> 1) + 1];
        int s0 = half ? q0.z : q0.x;
        int s1 = half ? q1.z : q1.x;
        float n0 = __int_as_float(half ? q0.w : q0.y);
        float n1 = __int_as_float(half ? q1.w : q1.y);
        float4 a0 = __ldg((const float4*)(h + (size_t)s0 * FO3P) + sub);
        float4 a1 = __ldg((const float4*)(h + (size_t)s1 * FO3P) + sub);
        acc.x = fmaf(a0.x, n0, acc.x); acc.y = fmaf(a0.y, n0, acc.y);
        acc.z = fmaf(a0.z, n0, acc.z); acc.w = fmaf(a0.w, n0, acc.w);
        acc.x = fmaf(a1.x, n1, acc.x); acc.y = fmaf(a1.y, n1, acc.y);
        acc.z = fmaf(a1.z, n1, acc.z); acc.w = fmaf(a1.w, n1, acc.w);
    }
    if (p + 2 <= p1) {
        int4 q = ep4[p >> 1];
        int s = half ? q.z : q.x;
        float nrm = __int_as_float(half ? q.w : q.y);
        float4 a = __ldg((const float4*)(h + (size_t)s * FO3P) + sub);
        acc.x = fmaf(a.x, nrm, acc.x); acc.y = fmaf(a.y, nrm, acc.y);
        acc.z = fmaf(a.z, nrm, acc.z); acc.w = fmaf(a.w, nrm, acc.w);
        p += 2;
    }
    if (p < p1) {
        int2 e = g_epack[p];
        float nrm = half ? 0.f : __int_as_float(e.y);
        float4 a = __ldg((const float4*)(h + (size_t)e.x * FO3P) + sub);
        acc.x = fmaf(a.x, nrm, acc.x); acc.y = fmaf(a.y, nrm, acc.y);
        acc.z = fmaf(a.z, nrm, acc.z); acc.w = fmaf(a.w, nrm, acc.w);
    }

    acc.x += __shfl_down_sync(MASK, acc.x, 16);
    acc.y += __shfl_down_sync(MASK, acc.y, 16);
    acc.z += __shfl_down_sync(MASK, acc.z, 16);
    acc.w += __shfl_down_sync(MASK, acc.w, 16);

    if (half == 0) {
        float4 bv = ((const float4*)bias)[sub];
        acc.x += bv.x; acc.y += bv.y; acc.z += bv.z; acc.w += bv.w;
        ((float4*)(out + (size_t)node * FO3))[sub] = acc;
    }
}

// ---------------- launch ----------------
extern "C" void kernel_launch(void* const* d_in, const int* in_sizes, int n_in,
                              void* d_out, int out_size) {
    const float* x  = (const float*)d_in[0];
    const void*  ei = d_in[1];
    const float* ew = (const float*)d_in[2];
    const float* W1 = (const float*)d_in[3];
    const float* b1 = (const float*)d_in[4];
    const float* W2 = (const float*)d_in[5];
    const float* b2 = (const float*)d_in[6];
    const float* W3 = (const float*)d_in[7];
    const float* b3 = (const float*)d_in[8];
    int n  = in_sizes[0] / NF;
    int nE = in_sizes[2];
    float* out = (float*)d_out;

    float *dinv, *h32;
    __half *hh, *yh, *w2h, *w3h;
    int *rowptr, *cur, *cnt, *bsum;
    cudaGetSymbolAddress((void**)&dinv, g_deg);
    cudaGetSymbolAddress((void**)&hh, g_hh);
    cudaGetSymbolAddress((void**)&h32, g_h32);
    cudaGetSymbolAddress((void**)&yh, g_yh);
    cudaGetSymbolAddress((void**)&w2h, g_w2h);
    cudaGetSymbolAddress((void**)&w3h, g_w3h);
    cudaGetSymbolAddress((void**)&rowptr, g_rowptr);
    cudaGetSymbolAddress((void**)&cur, g_cur);
    cudaGetSymbolAddress((void**)&cnt, g_cnt);
    cudaGetSymbolAddress((void**)&bsum, g_bsum);

    const int T = 256;
    const int TA = 64;
    size_t smemF32 = (size_t)(NF * NF + 8 * 8 * NF) * sizeof(float);
    size_t smemTC128 = 48 * 1024;
    size_t smemTC40  = 44 * 1024;
    cudaFuncSetAttribute(k_gemm128_f32, cudaFuncAttributeMaxDynamicSharedMemorySize, (int)smemF32);
    cudaFuncSetAttribute(k_gemm128_tc,  cudaFuncAttributeMaxDynamicSharedMemorySize, (int)smemTC128);
    cudaFuncSetAttribute(k_gemm40_tc,   cudaFuncAttributeMaxDynamicSharedMemorySize, (int)smemTC40);

    int gb64  = (n + 63) / 64;
    int gb128 = (n + 127) / 128;
    int ab = (n * 32 + TA - 1) / TA;
    int nb = (n + 1023) / 1024;

    cudaStream_t s2;
    cudaStreamCreateWithFlags(&s2, cudaStreamNonBlocking);
    cudaEvent_t evF, evJ;
    cudaEventCreateWithFlags(&evF, cudaEventDisableTiming);
    cudaEventCreateWithFlags(&evJ, cudaEventDisableTiming);

    cudaEventRecord(evF, 0);

    // Setup chain
    k_init<<<(n + T - 1) / T, T>>>((const long long*)ei, nE, W2, W3, w2h, w3h,
                                   dinv, cnt, n);
    k_prep<<<(nE + T - 1) / T, T>>>(ei, ew, dinv, cnt, nE);
    k_scanA<<<nb, 1024>>>(cnt, rowptr, bsum, n);
    k_scanCB<<<(n + T - 1) / T, T>>>(rowptr, bsum, cur, dinv, n, nE, nb);
    k_place<<<(nE + T - 1) / T, T>>>(ew, dinv, nE);

    // Fork branch: GEMM1 overlaps setup at replay
    cudaStreamWaitEvent(s2, evF, 0);
    k_gemm128_f32<<<gb64, T, smemF32, s2>>>(x, W1, hh, n);
    cudaEventRecord(evJ, s2);
    cudaStreamWaitEvent(0, evJ, 0);

    // Layer 1 agg
    k_agg128h<<<ab, TA>>>(hh, b1, dinv, yh, n);
    // Layer 2
    k_gemm128_tc<<<gb64, T, smemTC128>>>(yh, w2h, hh, n);
    k_agg128h<<<ab, TA>>>(hh, b2, dinv, yh, n);
    // Layer 3
    k_gemm40_tc<<<gb128, T, smemTC40>>>(yh, w3h, h32, n);
    k_agg40<<<ab, TA>>>(h32, b3, dinv, out, n);
}

// round 13
// speedup vs baseline: 1.1887x; 1.0299x over previous
#include <cuda_runtime.h>
#include <cuda_fp16.h>
#include <mma.h>
#include <cstdint>

using namespace nvcuda;

#define NN 100000
#define NE_CAP 1600000
#define NF 128
#define FO3 40
#define FO3P 48

typedef unsigned long long u64;

// ---------------- device scratch ----------------
__device__ float  g_deg[NN];
__device__ __half g_hh1[(size_t)NN * NF];   // layer-1 h
__device__ __half g_hh2[(size_t)NN * NF];   // layer-2 h (double buffer for pipeline)
__device__ __half g_yh[(size_t)NN * NF];    // y (agg outputs, layers 1,2)
__device__ __half g_h48[(size_t)NN * FO3P]; // layer-3 h, fp16, stride 48
__device__ __half g_w2h[NF * NF];
__device__ __half g_w3h[NF * FO3P];
__device__ int2   g_sd[NE_CAP];
__device__ int    g_rank[NE_CAP];
__device__ int2   g_epack[NE_CAP];
__device__ int    g_rowptr[NN + 1];
__device__ int    g_cnt[NN];
__device__ int    g_bsum[128];
__device__ int    g_is32;

// ---------------- f32x2 helpers ----------------
__device__ __forceinline__ void ffma2(u64& d, u64 a, u64 b) {
    asm("fma.rn.f32x2 %0, %1, %2, %0;" : "+l"(d) : "l"(a), "l"(b));
}
__device__ __forceinline__ u64 dup2(float x) {
    u64 r; asm("mov.b64 %0, {%1, %1};" : "=l"(r) : "f"(x)); return r;
}
__device__ __forceinline__ float2 upk2(u64 v) {
    float2 r; asm("mov.b64 {%0, %1}, %2;" : "=f"(r.x), "=f"(r.y) : "l"(v)); return r;
}

// ---------------- fused init ----------------
__global__ void k_init(const long long* __restrict__ raw, int nE,
                       const float* __restrict__ W2, const float* __restrict__ W3,
                       __half* __restrict__ W2h, __half* __restrict__ W3h,
                       float* deg, int* cnt, int n) {
    int tid = threadIdx.x;
    int gid = blockIdx.x * blockDim.x + tid;
    int gsz = gridDim.x * blockDim.x;

    if (blockIdx.x == 0) {
        __shared__ int sflag;
        if (tid == 0) sflag = 0;
        __syncthreads();
        int lim = nE < 4096 ? nE : 4096;
        int bad = 0;
        for (int i = tid; i < lim; i += blockDim.x) {
            long long v = raw[i];
            if (v < 0 || v >= (1LL << 30)) bad = 1;
        }
        if (bad) atomicOr(&sflag, 1);
        __syncthreads();
        if (tid == 0) g_is32 = sflag;
    }
    for (int i = gid; i < n; i += gsz) { deg[i] = 0.f; cnt[i] = 0; }
    for (int i = gid; i < NF * NF; i += gsz) W2h[i] = __float2half(W2[i]);
    for (int i = gid; i < NF * FO3P; i += gsz) {
        int r = i / FO3P, c = i - r * FO3P;
        W3h[i] = (c < FO3) ? __float2half(W3[r * FO3 + c]) : __half(0);
    }
}

__global__ void k_prep(const void* __restrict__ raw, const float* __restrict__ ew,
                       float* deg, int* cnt, int nE) {
    int e = blockIdx.x * blockDim.x + threadIdx.x;
    if (e >= nE) return;
    int s, d;
    if (g_is32) {
        const int* p = (const int*)raw;
        s = p[e]; d = p[(size_t)nE + e];
    } else {
        const long long* p = (const long long*)raw;
        s = (int)p[e]; d = (int)p[(size_t)nE + e];
    }
    g_sd[e] = make_int2(s, d);
    atomicAdd(&deg[d], ew[e]);
    g_rank[e] = atomicAdd(&cnt[d], 1);
}

__global__ void k_scanA(const int* __restrict__ cnt, int* rowptr, int* bsum, int n) {
    __shared__ int s[1024];
    int t = threadIdx.x, i = blockIdx.x * 1024 + t;
    int v = (i < n) ? cnt[i] : 0;
    s[t] = v;
    __syncthreads();
#pragma unroll
    for (int off = 1; off < 1024; off <<= 1) {
        int x = (t >= off) ? s[t - off] : 0;
        __syncthreads();
        s[t] += x;
        __syncthreads();
    }
    if (i < n) rowptr[i] = s[t] - v;
    if (t == 1023) bsum[blockIdx.x] = s[1023];
}

__global__ void k_scanCB(int* rowptr, const int* __restrict__ bsum,
                         float* deg, int n, int nE, int nb) {
    __shared__ int sb[128];
    int t = threadIdx.x;
    if (t < 128) sb[t] = (t < nb) ? bsum[t] : 0;
    __syncthreads();
#pragma unroll
    for (int off = 1; off < 128; off <<= 1) {
        int x = 0;
        if (t < 128 && t >= off) x = sb[t - off];
        __syncthreads();
        if (t < 128) sb[t] += x;
        __syncthreads();
    }
    int i = blockIdx.x * blockDim.x + t;
    if (i < n) {
        int j = i >> 10;
        int off = (j == 0) ? 0 : sb[j - 1];
        rowptr[i] += off;
        deg[i] = rsqrtf(deg[i] + 1.0f);
    }
    if (i == 0) rowptr[n] = nE;
}

// atomic-free placement: slot = rowptr[dst] + rank (captured in prep)
__global__ void k_place(const float* __restrict__ ew, const float* __restrict__ dinv,
                        int nE) {
    int e = blockIdx.x * blockDim.x + threadIdx.x;
    if (e >= nE) return;
    int2 sd = g_sd[e];
    int p = g_rowptr[sd.y] + g_rank[e];
    float norm = ew[e] * dinv[sd.x] * dinv[sd.y];
    g_epack[p] = make_int2(sd.x, __float_as_int(norm));
}

// ---------------- layer-1 GEMM (fp32, FFMA2) -> fp16 ----------------
__global__ void __launch_bounds__(256, 2)
k_gemm128_f32(const float* __restrict__ X, const float* __restrict__ W,
              __half* __restrict__ Hh, int n) {
    extern __shared__ float sm[];
    float* Ws = sm;
    float* Xs = sm + NF * NF;
    int tid = threadIdx.x, warp = tid >> 5, lane = tid & 31;

    for (int i = tid; i < NF * NF / 4; i += 256)
        ((float4*)Ws)[i] = ((const float4*)W)[i];

    int row0 = blockIdx.x * 64 + warp * 8;
    float* xs = Xs + warp * (8 * NF);
#pragma unroll
    for (int r = 0; r < 8; r++) {
        int row = row0 + r;
        float4 v = make_float4(0.f, 0.f, 0.f, 0.f);
        if (row < n) v = ((const float4*)(X + (size_t)row * NF))[lane];
        ((float4*)(xs + r * NF))[lane] = v;
    }
    __syncthreads();

    u64 acc[8][2];
#pragma unroll
    for (int r = 0; r < 8; r++) { acc[r][0] = 0ull; acc[r][1] = 0ull; }

    const float* wl = Ws + 4 * lane;
    for (int k4 = 0; k4 < NF; k4 += 4) {
        float4 xv[8];
#pragma unroll
        for (int r = 0; r < 8; r++)
            xv[r] = *(const float4*)(xs + r * NF + k4);
#pragma unroll
        for (int kk = 0; kk < 4; kk++) {
            const float* wp = wl + (k4 + kk) * NF;
            u64 w01 = *(const u64*)(wp);
            u64 w23 = *(const u64*)(wp + 2);
#pragma unroll
            for (int r = 0; r < 8; r++) {
                float xk = kk == 0 ? xv[r].x : kk == 1 ? xv[r].y
                         : kk == 2 ? xv[r].z : xv[r].w;
                u64 xk2 = dup2(xk);
                ffma2(acc[r][0], xk2, w01);
                ffma2(acc[r][1], xk2, w23);
            }
        }
    }
#pragma unroll
    for (int r = 0; r < 8; r++) {
        int row = row0 + r;
        if (row < n) {
            float2 a = upk2(acc[r][0]), b = upk2(acc[r][1]);
            __half2 h01 = __floats2half2_rn(a.x, a.y);
            __half2 h23 = __floats2half2_rn(b.x, b.y);
            ((uint2*)(Hh + (size_t)row * NF))[lane] =
                make_uint2(*(unsigned*)&h01, *(unsigned*)&h23);
        }
    }
}

// ---------------- tc GEMM fout=128 (fp16 X offset by caller) ----------------
__global__ void __launch_bounds__(256, 2)
k_gemm128_tc(const __half* __restrict__ X, const __half* __restrict__ W,
             __half* __restrict__ Hh, int n) {
    extern __shared__ char smc[];
    __half* Ws = (__half*)smc;
    __half* Xs = (__half*)(smc + 32 * 1024);
    int tid = threadIdx.x, wid = tid >> 5;
    int warp_m = wid >> 1, warp_n = wid & 1;
    int row0 = blockIdx.x * 64;

    for (int i = tid; i < 2048; i += 256)
        ((uint4*)Ws)[i] = ((const uint4*)W)[i];
    __half2 z2 = __floats2half2_rn(0.f, 0.f);
    for (int i = tid; i < 1024; i += 256) {
        int row = i >> 4, c = i & 15;
        uint4 v = make_uint4(0, 0, 0, 0);
        if (row0 + row < n) {
            v = ((const uint4*)(X + (size_t)(row0 + row) * NF))[c];
            __half2* hv = (__half2*)&v;
            hv[0] = __hmax2(hv[0], z2); hv[1] = __hmax2(hv[1], z2);
            hv[2] = __hmax2(hv[2], z2); hv[3] = __hmax2(hv[3], z2);
        }
        ((uint4*)Xs)[i] = v;
    }
    __syncthreads();

    wmma::fragment<wmma::accumulator, 16, 16, 16, float> c[4];
#pragma unroll
    for (int j = 0; j < 4; j++) wmma::fill_fragment(c[j], 0.f);

#pragma unroll
    for (int k0 = 0; k0 < NF; k0 += 16) {
        wmma::fragment<wmma::matrix_a, 16, 16, 16, __half, wmma::row_major> a;
        wmma::load_matrix_sync(a, Xs + warp_m * 16 * NF + k0, NF);
#pragma unroll
        for (int j = 0; j < 4; j++) {
            wmma::fragment<wmma::matrix_b, 16, 16, 16, __half, wmma::row_major> b;
            wmma::load_matrix_sync(b, Ws + k0 * NF + warp_n * 64 + j * 16, NF);
            wmma::mma_sync(c[j], a, b, c[j]);
        }
    }
    __syncthreads();
    float* Cs = (float*)smc;
#pragma unroll
    for (int j = 0; j < 4; j++)
        wmma::store_matrix_sync(Cs + warp_m * 16 * NF + warp_n * 64 + j * 16,
                                c[j], NF, wmma::mem_row_major);
    __syncthreads();

    for (int i = tid; i < 64 * 32; i += 256) {
        int row = i >> 5, g = i & 31;
        if (row0 + row < n) {
            float4 v = ((const float4*)Cs)[i];
            __half2 h01 = __floats2half2_rn(v.x, v.y);
            __half2 h23 = __floats2half2_rn(v.z, v.w);
            ((uint2*)(Hh + (size_t)(row0 + row) * NF))[g] =
                make_uint2(*(unsigned*)&h01, *(unsigned*)&h23);
        }
    }
}

// ---------------- tc GEMM fout=48 -> fp16 h48 ----------------
__global__ void __launch_bounds__(256, 2)
k_gemm40_tc(const __half* __restrict__ X, const __half* __restrict__ W,
            __half* __restrict__ H48, int n) {
    extern __shared__ char smc[];
    __half* Ws = (__half*)smc;
    __half* Xs = (__half*)(smc + 12 * 1024);
    int tid = threadIdx.x, wid = tid >> 5;
    int row0 = blockIdx.x * 128;

    for (int i = tid; i < NF * FO3P / 8; i += 256)
        ((uint4*)Ws)[i] = ((const uint4*)W)[i];
    __half2 z2 = __floats2half2_rn(0.f, 0.f);
    for (int i = tid; i < 2048; i += 256) {
        int row = i >> 4, c = i & 15;
        uint4 v = make_uint4(0, 0, 0, 0);
        if (row0 + row < n) {
            v = ((const uint4*)(X + (size_t)(row0 + row) * NF))[c];
            __half2* hv = (__half2*)&v;
            hv[0] = __hmax2(hv[0], z2); hv[1] = __hmax2(hv[1], z2);
            hv[2] = __hmax2(hv[2], z2); hv[3] = __hmax2(hv[3], z2);
        }
        ((uint4*)Xs)[i] = v;
    }
    __syncthreads();

    wmma::fragment<wmma::accumulator, 16, 16, 16, float> c[3];
#pragma unroll
    for (int j = 0; j < 3; j++) wmma::fill_fragment(c[j], 0.f);

#pragma unroll
    for (int k0 = 0; k0 < NF; k0 += 16) {
        wmma::fragment<wmma::matrix_a, 16, 16, 16, __half, wmma::row_major> a;
        wmma::load_matrix_sync(a, Xs + wid * 16 * NF + k0, NF);
#pragma unroll
        for (int j = 0; j < 3; j++) {
            wmma::fragment<wmma::matrix_b, 16, 16, 16, __half, wmma::row_major> b;
            wmma::load_matrix_sync(b, Ws + k0 * FO3P + j * 16, FO3P);
            wmma::mma_sync(c[j], a, b, c[j]);
        }
    }
    __syncthreads();
    float* Cs = (float*)smc;
#pragma unroll
    for (int j = 0; j < 3; j++)
        wmma::store_matrix_sync(Cs + wid * 16 * FO3P + j * 16, c[j], FO3P,
                                wmma::mem_row_major);
    __syncthreads();

    // pack 48 fp32 -> 48 fp16 per row: 6 uint4 (8 halves each)
    for (int i = tid; i < 128 * 6; i += 256) {
        int row = i / 6, g = i - row * 6;
        int grow = row0 + row;
        if (grow < n) {
            const float* cp = Cs + row * FO3P + g * 8;
            __half2 p0 = __floats2half2_rn(cp[0], cp[1]);
            __half2 p1 = __floats2half2_rn(cp[2], cp[3]);
            __half2 p2 = __floats2half2_rn(cp[4], cp[5]);
            __half2 p3 = __floats2half2_rn(cp[6], cp[7]);
            ((uint4*)(H48 + (size_t)grow * FO3P))[g] =
                make_uint4(*(unsigned*)&p0, *(unsigned*)&p1,
                           *(unsigned*)&p2, *(unsigned*)&p3);
        }
    }
}

// ---------------- agg fp16, half-warp-per-edge, node range [nbase,nend) ----------
#define ACC8H(av, nrm)                                                     \
    {                                                                      \
        float2 u0 = __half22float2(*(const __half2*)&(av).x);              \
        float2 u1 = __half22float2(*(const __half2*)&(av).y);              \
        float2 u2 = __half22float2(*(const __half2*)&(av).z);              \
        float2 u3 = __half22float2(*(const __half2*)&(av).w);              \
        acc0.x = fmaf(u0.x, nrm, acc0.x); acc0.y = fmaf(u0.y, nrm, acc0.y);\
        acc0.z = fmaf(u1.x, nrm, acc0.z); acc0.w = fmaf(u1.y, nrm, acc0.w);\
        acc1.x = fmaf(u2.x, nrm, acc1.x); acc1.y = fmaf(u2.y, nrm, acc1.y);\
        acc1.z = fmaf(u3.x, nrm, acc1.z); acc1.w = fmaf(u3.y, nrm, acc1.w);\
    }

__global__ void k_agg128h(const __half* __restrict__ h, const float* __restrict__ bias,
                          const float* __restrict__ dinv, __half* __restrict__ outh,
                          int nbase, int nend) {
    int node = nbase + ((blockIdx.x * blockDim.x + threadIdx.x) >> 5);
    int lane = threadIdx.x & 31;
    if (node >= nend) return;
    int half = lane >> 4, sub = lane & 15;
    const uint4* h4 = (const uint4*)h;
    float dv = dinv[node];
    float selfn = half ? 0.f : dv * dv;

    uint4 sp = __ldg(&h4[(size_t)node * 16 + sub]);
    float4 acc0 = make_float4(0.f, 0.f, 0.f, 0.f);
    float4 acc1 = make_float4(0.f, 0.f, 0.f, 0.f);
    ACC8H(sp, selfn)

    int p = g_rowptr[node], p1 = g_rowptr[node + 1];
    if ((p & 1) && p < p1) {
        int2 e = g_epack[p];
        float nrm = half ? 0.f : __int_as_float(e.y);
        uint4 a = __ldg(&h4[(size_t)e.x * 16 + sub]);
        ACC8H(a, nrm)
        p++;
    }
    const int4* ep4 = (const int4*)g_epack;
    for (; p + 4 <= p1; p += 4) {
        int4 q0 = ep4[p >> 1], q1 = ep4[(p >> 1) + 1];
        int s0 = half ? q0.z : q0.x;
        int s1 = half ? q1.z : q1.x;
        float n0 = __int_as_float(half ? q0.w : q0.y);
        float n1 = __int_as_float(half ? q1.w : q1.y);
        uint4 a0 = __ldg(&h4[(size_t)s0 * 16 + sub]);
        uint4 a1 = __ldg(&h4[(size_t)s1 * 16 + sub]);
        ACC8H(a0, n0)
        ACC8H(a1, n1)
    }
    if (p + 2 <= p1) {
        int4 q = ep4[p >> 1];
        int s = half ? q.z : q.x;
        float nrm = __int_as_float(half ? q.w : q.y);
        uint4 a = __ldg(&h4[(size_t)s * 16 + sub]);
        ACC8H(a, nrm)
        p += 2;
    }
    if (p < p1) {
        int2 e = g_epack[p];
        float nrm = half ? 0.f : __int_as_float(e.y);
        uint4 a = __ldg(&h4[(size_t)e.x * 16 + sub]);
        ACC8H(a, nrm)
    }

    acc0.x += __shfl_down_sync(0xffffffffu, acc0.x, 16);
    acc0.y += __shfl_down_sync(0xffffffffu, acc0.y, 16);
    acc0.z += __shfl_down_sync(0xffffffffu, acc0.z, 16);
    acc0.w += __shfl_down_sync(0xffffffffu, acc0.w, 16);
    acc1.x += __shfl_down_sync(0xffffffffu, acc1.x, 16);
    acc1.y += __shfl_down_sync(0xffffffffu, acc1.y, 16);
    acc1.z += __shfl_down_sync(0xffffffffu, acc1.z, 16);
    acc1.w += __shfl_down_sync(0xffffffffu, acc1.w, 16);

    if (half == 0) {
        float4 b0 = ((const float4*)bias)[2 * sub];
        float4 b1 = ((const float4*)bias)[2 * sub + 1];
        acc0.x += b0.x; acc0.y += b0.y; acc0.z += b0.z; acc0.w += b0.w;
        acc1.x += b1.x; acc1.y += b1.y; acc1.z += b1.z; acc1.w += b1.w;
        __half2 o0 = __floats2half2_rn(acc0.x, acc0.y);
        __half2 o1 = __floats2half2_rn(acc0.z, acc0.w);
        __half2 o2 = __floats2half2_rn(acc1.x, acc1.y);
        __half2 o3 = __floats2half2_rn(acc1.z, acc1.w);
        ((uint4*)outh)[(size_t)node * 16 + sub] =
            make_uint4(*(unsigned*)&o0, *(unsigned*)&o1,
                       *(unsigned*)&o2, *(unsigned*)&o3);
    }
}

// ---------------- agg40: fp16 h48 (stride 48), half-warp-per-edge ----------------
__global__ void k_agg40(const __half* __restrict__ h, const float* __restrict__ bias,
                        const float* __restrict__ dinv, float* __restrict__ out,
                        int n) {
    int node = (blockIdx.x * blockDim.x + threadIdx.x) >> 5;
    int lane = threadIdx.x & 31;
    if (node >= n) return;
    int half = lane >> 4, sub = lane & 15;
    if (sub >= 10) return;              // 10 x uint2 (4 halves) = 40 cols
    const unsigned MASK = 0x03FF03FFu;
    float dv = dinv[node];
    float selfn = half ? 0.f : dv * dv;

    uint2 sp = __ldg((const uint2*)(h + (size_t)node * FO3P) + sub);
    float4 acc = make_float4(0.f, 0.f, 0.f, 0.f);
#define ACC4H(av, nrm)                                                    \
    {                                                                     \
        float2 u0 = __half22float2(*(const __half2*)&(av).x);             \
        float2 u1 = __half22float2(*(const __half2*)&(av).y);             \
        acc.x = fmaf(u0.x, nrm, acc.x); acc.y = fmaf(u0.y, nrm, acc.y);   \
        acc.z = fmaf(u1.x, nrm, acc.z); acc.w = fmaf(u1.y, nrm, acc.w);   \
    }
    ACC4H(sp, selfn)

    int p = g_rowptr[node], p1 = g_rowptr[node + 1];
    if ((p & 1) && p < p1) {
        int2 e = g_epack[p];
        float nrm = half ? 0.f : __int_as_float(e.y);
        uint2 a = __ldg((const uint2*)(h + (size_t)e.x * FO3P) + sub);
        ACC4H(a, nrm)
        p++;
    }
    const int4* ep4 = (const int4*)g_epack;
    for (; p + 4 <= p1; p += 4) {
        int4 q0 = ep4[p >> 1], q1 = ep4[(p >> 1) + 1];
        int s0 = half ? q0.z : q0.x;
        int s1 = half ? q1.z : q1.x;
        float n0 = __int_as_float(half ? q0.w : q0.y);
        float n1 = __int_as_float(half ? q1.w : q1.y);
        uint2 a0 = __ldg((const uint2*)(h + (size_t)s0 * FO3P) + sub);
        uint2 a1 = __ldg((const uint2*)(h + (size_t)s1 * FO3P) + sub);
        ACC4H(a0, n0)
        ACC4H(a1, n1)
    }
    if (p + 2 <= p1) {
        int4 q = ep4[p >> 1];
        int s = half ? q.z : q.x;
        float nrm = __int_as_float(half ? q.w : q.y);
        uint2 a = __ldg((const uint2*)(h + (size_t)s * FO3P) + sub);
        ACC4H(a, nrm)
        p += 2;
    }
    if (p < p1) {
        int2 e = g_epack[p];
        float nrm = half ? 0.f : __int_as_float(e.y);
        uint2 a = __ldg((const uint2*)(h + (size_t)e.x * FO3P) + sub);
        ACC4H(a, nrm)
    }
#undef ACC4H

    acc.x += __shfl_down_sync(MASK, acc.x, 16);
    acc.y += __shfl_down_sync(MASK, acc.y, 16);
    acc.z += __shfl_down_sync(MASK, acc.z, 16);
    acc.w += __shfl_down_sync(MASK, acc.w, 16);

    if (half == 0) {
        float4 bv = ((const float4*)bias)[sub];
        acc.x += bv.x; acc.y += bv.y; acc.z += bv.z; acc.w += bv.w;
        ((float4*)(out + (size_t)node * FO3))[sub] = acc;
    }
}

// ---------------- launch ----------------
extern "C" void kernel_launch(void* const* d_in, const int* in_sizes, int n_in,
                              void* d_out, int out_size) {
    const float* x  = (const float*)d_in[0];
    const void*  ei = d_in[1];
    const float* ew = (const float*)d_in[2];
    const float* W1 = (const float*)d_in[3];
    const float* b1 = (const float*)d_in[4];
    const float* W2 = (const float*)d_in[5];
    const float* b2 = (const float*)d_in[6];
    const float* W3 = (const float*)d_in[7];
    const float* b3 = (const float*)d_in[8];
    int n  = in_sizes[0] / NF;
    int nE = in_sizes[2];
    float* out = (float*)d_out;

    float* dinv;
    __half *hh1, *hh2, *yh, *h48, *w2h, *w3h;
    int *rowptr, *cnt, *bsum;
    cudaGetSymbolAddress((void**)&dinv, g_deg);
    cudaGetSymbolAddress((void**)&hh1, g_hh1);
    cudaGetSymbolAddress((void**)&hh2, g_hh2);
    cudaGetSymbolAddress((void**)&yh, g_yh);
    cudaGetSymbolAddress((void**)&h48, g_h48);
    cudaGetSymbolAddress((void**)&w2h, g_w2h);
    cudaGetSymbolAddress((void**)&w3h, g_w3h);
    cudaGetSymbolAddress((void**)&rowptr, g_rowptr);
    cudaGetSymbolAddress((void**)&cnt, g_cnt);
    cudaGetSymbolAddress((void**)&bsum, g_bsum);

    const int T = 256;
    const int TA = 64;
    size_t smemF32 = (size_t)(NF * NF + 8 * 8 * NF) * sizeof(float);
    size_t smemTC128 = 48 * 1024;
    size_t smemTC40  = 44 * 1024;
    cudaFuncSetAttribute(k_gemm128_f32, cudaFuncAttributeMaxDynamicSharedMemorySize, (int)smemF32);
    cudaFuncSetAttribute(k_gemm128_tc,  cudaFuncAttributeMaxDynamicSharedMemorySize, (int)smemTC128);
    cudaFuncSetAttribute(k_gemm40_tc,   cudaFuncAttributeMaxDynamicSharedMemorySize, (int)smemTC40);

    int gb64  = (n + 63) / 64;
    int nb = (n + 1023) / 1024;

    // Node split for pipeline (128-aligned for both GEMM tile sizes)
    int nA = ((n / 2 + 127) / 128) * 128;
    if (nA > n) nA = n;
    int nB = n - nA;
    int gbA64 = (nA + 63) / 64,   gbB64 = (nB + 63) / 64;
    int gbA40 = (nA + 127) / 128, gbB40 = (nB + 127) / 128;
    int abA = (nA * 32 + TA - 1) / TA;
    int abB = (nB * 32 + TA - 1) / TA;
    int ab  = (n * 32 + TA - 1) / TA;

    cudaStream_t s2;
    cudaStreamCreateWithFlags(&s2, cudaStreamNonBlocking);
    cudaEvent_t evF, evJ, ev1, ev2, ev3, ev4;
    cudaEventCreateWithFlags(&evF, cudaEventDisableTiming);
    cudaEventCreateWithFlags(&evJ, cudaEventDisableTiming);
    cudaEventCreateWithFlags(&ev1, cudaEventDisableTiming);
    cudaEventCreateWithFlags(&ev2, cudaEventDisableTiming);
    cudaEventCreateWithFlags(&ev3, cudaEventDisableTiming);
    cudaEventCreateWithFlags(&ev4, cudaEventDisableTiming);

    cudaEventRecord(evF, 0);

    // Setup chain on s0
    k_init<<<(n + T - 1) / T, T>>>((const long long*)ei, nE, W2, W3, w2h, w3h,
                                   dinv, cnt, n);
    k_prep<<<(nE + T - 1) / T, T>>>(ei, ew, dinv, cnt, nE);
    k_scanA<<<nb, 1024>>>(cnt, rowptr, bsum, n);
    k_scanCB<<<(n + T - 1) / T, T>>>(rowptr, bsum, dinv, n, nE, nb);
    k_place<<<(nE + T - 1) / T, T>>>(ew, dinv, nE);

    // GEMM1 on s2, overlapping setup
    cudaStreamWaitEvent(s2, evF, 0);
    k_gemm128_f32<<<gb64, T, smemF32, s2>>>(x, W1, hh1, n);
    cudaEventRecord(evJ, s2);
    cudaStreamWaitEvent(0, evJ, 0);

    // ---- Pipelined layers: agg (L2-bound) overlaps GEMM (tensor-bound) ----
    // agg1_A
    k_agg128h<<<abA, TA>>>(hh1, b1, dinv, yh, 0, nA);
    cudaEventRecord(ev1, 0);
    // gemm2_A (s2) || agg1_B (s0)
    cudaStreamWaitEvent(s2, ev1, 0);
    k_gemm128_tc<<<gbA64, T, smemTC128, s2>>>(yh, w2h, hh2, nA);
    cudaEventRecord(ev2, s2);
    if (nB > 0) {
        k_agg128h<<<abB, TA>>>(hh1, b1, dinv, yh, nA, n);
        k_gemm128_tc<<<gbB64, T, smemTC128>>>(yh + (size_t)nA * NF, w2h,
                                              hh2 + (size_t)nA * NF, nB);
    }
    cudaStreamWaitEvent(0, ev2, 0);
    // agg2_A
    k_agg128h<<<abA, TA>>>(hh2, b2, dinv, yh, 0, nA);
    cudaEventRecord(ev3, 0);
    // gemm40_A (s2) || agg2_B (s0)
    cudaStreamWaitEvent(s2, ev3, 0);
    k_gemm40_tc<<<gbA40, T, smemTC40, s2>>>(yh, w3h, h48, nA);
    cudaEventRecord(ev4, s2);
    if (nB > 0) {
        k_agg128h<<<abB, TA>>>(hh2, b2, dinv, yh, nA, n);
        k_gemm40_tc<<<gbB40, T, smemTC40>>>(yh + (size_t)nA * NF, w3h,
                                            h48 + (size_t)nA * FO3P, nB);
    }
    cudaStreamWaitEvent(0, ev4, 0);
    // final agg -> d_out
    k_agg40<<<ab, TA>>>(h48, b3, dinv, out, n);
}